// round 13
// baseline (speedup 1.0000x reference)
#include <cuda_runtime.h>
#include <cuda_bf16.h>
#include <cstdint>

#define B      2
#define NNODE  50000
#define IN_DIM 64
#define HID    256
#define OUT    128
#define NEDGE  500000
#define TOTAL_NODES (B * NNODE)

// fp32 node/decode tiles (proven R7 config)
#define MPB 32
#define DPB 16
#define RS  36
#define HS_RS (HID + 4)

// edge tensor kernel: 64 edges x 2 batches = 128 M-rows per block
#define KS1  264     // A1/B1 row stride (bf16): 128 hi + 128 lo + 8 pad
#define KS2  520     // A2/B2 row stride (bf16): 256 hi + 256 lo + 8 pad
#define DHS  68      // Dh row stride (f32)
// dynamic smem offsets (bytes)
#define OFF_A1  0        // 128*264*2 = 67584
#define OFF_B1  67584    // 256*264*2 = 135168 -> ends 202752
#define OFF_A2  0        // 128*520*2 = 133120 (overlays A1+B1 after GEMM1)
#define OFF_B2  133120   // 64*520*2  = 66560  -> ends 199680
#define OFF_DH  199680   // 64*68*4   = 17408  -> ends 217088
#define EDGE_DSMEM 217088

// ---------------------------------------------------------------------------
// device globals (allocation-guard-safe)
// ---------------------------------------------------------------------------
__device__ float g_H[(size_t)B * NNODE * OUT];
__device__ int   g_eu[NEDGE];
__device__ int   g_ev[NEDGE];
__device__ int   g_is64;
// pre-split, pre-transposed bf16 weight images [n][k']:
__device__ __align__(16) __nv_bfloat16 g_B1bf[256 * KS1]; // ew1: hi at k, lo at 128+k
__device__ __align__(16) __nv_bfloat16 g_B2bf[128 * KS2]; // ew2: hi at k, lo at 256+k

// ---------------------------------------------------------------------------
// helpers
// ---------------------------------------------------------------------------
static __device__ __forceinline__ void mma16816(float* d, const uint32_t* a, const uint32_t* b)
{
    asm volatile(
        "mma.sync.aligned.m16n8k16.row.col.f32.bf16.bf16.f32 "
        "{%0,%1,%2,%3}, {%4,%5,%6,%7}, {%8,%9}, {%0,%1,%2,%3};"
        : "+f"(d[0]), "+f"(d[1]), "+f"(d[2]), "+f"(d[3])
        : "r"(a[0]), "r"(a[1]), "r"(a[2]), "r"(a[3]), "r"(b[0]), "r"(b[1]));
}

static __device__ __forceinline__ void ldsm4(uint32_t& r0, uint32_t& r1, uint32_t& r2,
                                             uint32_t& r3, uint32_t addr)
{
    asm volatile("ldmatrix.sync.aligned.m8n8.x4.shared.b16 {%0,%1,%2,%3}, [%4];"
                 : "=r"(r0), "=r"(r1), "=r"(r2), "=r"(r3) : "r"(addr));
}

static __device__ __forceinline__ void cp16(uint32_t dst, const void* src)
{
    asm volatile("cp.async.cg.shared.global [%0], [%1], 16;" :: "r"(dst), "l"(src) : "memory");
}
#define CP_COMMIT() asm volatile("cp.async.commit_group;" ::: "memory")
#define CP_WAIT0()  asm volatile("cp.async.wait_group 0;" ::: "memory")

static __device__ __forceinline__ void red_add_v4(float* p, float a, float b, float c, float d)
{
    asm volatile("red.global.add.v4.f32 [%0], {%1, %2, %3, %4};"
                 :: "l"(p), "f"(a), "f"(b), "f"(c), "f"(d) : "memory");
}

static __device__ __forceinline__ void split_store(__nv_bfloat16* hi_p, __nv_bfloat16* lo_p,
                                                   float v0, float v1)
{
    __nv_bfloat162 hp = __floats2bfloat162_rn(v0, v1);
    const float h0 = __bfloat162float(hp.x), h1 = __bfloat162float(hp.y);
    __nv_bfloat162 lp = __floats2bfloat162_rn(v0 - h0, v1 - h1);
    *(uint32_t*)hi_p = *(const uint32_t*)&hp;
    *(uint32_t*)lo_p = *(const uint32_t*)&lp;
}

// ---------------------------------------------------------------------------
// edge dtype detect + SoA normalize (proven)
// ---------------------------------------------------------------------------
__global__ void detect_edge_dtype_kernel(const int* __restrict__ e32)
{
    if (threadIdx.x == 0 && blockIdx.x == 0) {
        int all_zero = 1;
        #pragma unroll 1
        for (int i = 1; i < 256; i += 2)
            if (e32[i] != 0) { all_zero = 0; break; }
        g_is64 = all_zero;
    }
}

__global__ __launch_bounds__(256) void convert_edges_kernel(const int* __restrict__ e32)
{
    const int e = blockIdx.x * 256 + threadIdx.x;
    if (e < NEDGE) {
        if (g_is64) { g_eu[e] = e32[4 * e + 0]; g_ev[e] = e32[4 * e + 2]; }
        else        { g_eu[e] = e32[2 * e + 0]; g_ev[e] = e32[2 * e + 1]; }
    }
}

// ---------------------------------------------------------------------------
// weight prep: split fp32 -> bf16 hi/lo, transpose to [n][k]
// ---------------------------------------------------------------------------
__global__ __launch_bounds__(256) void prep_weights_kernel(
    const float* __restrict__ ew1, const float* __restrict__ ew2)
{
    const int tid = blockIdx.x * 256 + threadIdx.x;
    const int stride = gridDim.x * 256;
    for (int idx = tid; idx < 256 * 128; idx += stride) {
        const int n = idx >> 7, k = idx & 127;
        const float w = ew1[k * HID + n];
        const __nv_bfloat16 hi = __float2bfloat16_rn(w);
        g_B1bf[n * KS1 + k]       = hi;
        g_B1bf[n * KS1 + 128 + k] = __float2bfloat16_rn(w - __bfloat162float(hi));
    }
    for (int idx = tid; idx < 128 * 256; idx += stride) {
        const int n = idx >> 8, k = idx & 255;
        const float w = ew2[k * OUT + n];
        const __nv_bfloat16 hi = __float2bfloat16_rn(w);
        g_B2bf[n * KS2 + k]       = hi;
        g_B2bf[n * KS2 + 256 + k] = __float2bfloat16_rn(w - __bfloat162float(hi));
    }
}

// ---------------------------------------------------------------------------
// Edge MLP v8: fused-batch split-bf16 mma.sync + ldmatrix + cp.async overlap
// ---------------------------------------------------------------------------
__global__ __launch_bounds__(256, 1) void edge_mlp_tc_kernel(
    const float* __restrict__ x,
    const float* __restrict__ eb1, const float* __restrict__ eb2)
{
    extern __shared__ __align__(16) char smc[];
    __nv_bfloat16* A1 = (__nv_bfloat16*)(smc + OFF_A1);
    __nv_bfloat16* B1 = (__nv_bfloat16*)(smc + OFF_B1);
    __nv_bfloat16* A2 = (__nv_bfloat16*)(smc + OFF_A2);
    float*         Dh = (float*)(smc + OFF_DH);

    __shared__ int   us[64], vs[64];
    __shared__ float eb1f[HID], eb2f[OUT];

    const int t   = threadIdx.x;
    const int wid = t >> 5;
    const int lid = t & 31;
    const int g   = lid >> 2;
    const int tg  = lid & 3;
    const int lr  = lid & 7;          // ldmatrix lane row
    const int lq  = (lid >> 3) & 1;   // ldmatrix quad bit
    const int lh  = lid >> 4;         // ldmatrix half bit
    const int e0  = blockIdx.x * 64;
    const int count = min(64, NEDGE - e0);

    const uint32_t sA1 = (uint32_t)__cvta_generic_to_shared(A1);
    const uint32_t sB1 = (uint32_t)__cvta_generic_to_shared(B1);
    const uint32_t sA2 = (uint32_t)__cvta_generic_to_shared(A2);
    const uint32_t sB2 = (uint32_t)__cvta_generic_to_shared(smc + OFF_B2);

    if (t < 64) {
        const int e = min(e0 + t, NEDGE - 1);
        us[t] = g_eu[e]; vs[t] = g_ev[e];
    }
    eb1f[t] = eb1[t];
    if (t < OUT) eb2f[t] = eb2[t];

    // prefetch B1 (all 256 n-rows, 135168 B) via cp.async — overlaps gather
    {
        const float4* src = (const float4*)g_B1bf;
        #pragma unroll 1
        for (int i = t; i < 8448; i += 256)
            cp16(sB1 + i * 16, src + i);
        CP_COMMIT();
    }
    __syncthreads();   // us/vs visible for gather

    // gather: rows 0-63 batch0, 64-127 batch1; split hi|lo into A1
    #pragma unroll
    for (int it = 0; it < 32; it++) {
        const int q = t + it * 256;                   // 8192 float2
        const int m = q >> 6;
        const int c = (q & 63) * 2;
        const int node = (c < IN_DIM) ? us[m & 63] : vs[m & 63];
        const float2 xv = *(const float2*)
            &x[((size_t)(m >> 6) * NNODE + node) * IN_DIM + (c & (IN_DIM - 1))];
        split_store(A1 + m * KS1 + c, A1 + m * KS1 + 128 + c, xv.x, xv.y);
    }
    CP_WAIT0();
    __syncthreads();

    // ---- GEMM1: warp tile 64m x 32n, both 128-n halves (ldmatrix frags) ----
    const int m1 = (wid >> 2) * 64;
    const int n1 = (wid & 3) * 32;
    uint32_t aAddr1[4], bAddr1[4];
    #pragma unroll
    for (int mi = 0; mi < 4; mi++)
        aAddr1[mi] = sA1 + ((m1 + mi * 16 + lr + lq * 8) * KS1 + lh * 8) * 2;
    #pragma unroll
    for (int h = 0; h < 2; h++)
        #pragma unroll
        for (int grp = 0; grp < 2; grp++)
            bAddr1[h * 2 + grp] = sB1 + ((h * 128 + n1 + grp * 16 + lh * 8 + lr) * KS1 + lq * 8) * 2;

    float acc1[2][4][4][4] = {};
    #pragma unroll 1
    for (int seg = 0; seg < 3; seg++) {
        const int aofs = ((seg == 1) ? 128 : 0) * 2;
        const int bofs = ((seg == 2) ? 128 : 0) * 2;
        #pragma unroll 2
        for (int k16 = 0; k16 < 8; k16++) {
            const int ka = aofs + k16 * 32;
            const int kb = bofs + k16 * 32;
            uint32_t a[4][4], bb[4][4];
            #pragma unroll
            for (int mi = 0; mi < 4; mi++)
                ldsm4(a[mi][0], a[mi][1], a[mi][2], a[mi][3], aAddr1[mi] + ka);
            #pragma unroll
            for (int j = 0; j < 4; j++)
                ldsm4(bb[j][0], bb[j][1], bb[j][2], bb[j][3], bAddr1[j] + kb);
            #pragma unroll
            for (int h = 0; h < 2; h++)
                #pragma unroll
                for (int nt = 0; nt < 4; nt++) {
                    const uint32_t* bp = (nt & 1) ? &bb[h * 2 + (nt >> 1)][2]
                                                  : &bb[h * 2 + (nt >> 1)][0];
                    #pragma unroll
                    for (int mi = 0; mi < 4; mi++)
                        mma16816(acc1[h][mi][nt], a[mi], bp);
                }
        }
    }
    __syncthreads();   // all GEMM1 reads done; A2 overlays A1 + B1[rows<124]

    // prefetch B2 half 0 (66560 B into [133120,199680) = B1 rows>=124, dead now)
    {
        const float4* src = (const float4*)g_B2bf;
        #pragma unroll 1
        for (int i = t; i < 4160; i += 256)
            cp16(sB2 + i * 16, src + i);
        CP_COMMIT();
    }

    // epilogue G1: bias + relu + split -> A2 [128m][256hi|256lo] (overlaps cp.async)
    #pragma unroll
    for (int h = 0; h < 2; h++) {
        #pragma unroll
        for (int mi = 0; mi < 4; mi++) {
            const int r0 = m1 + mi * 16 + g;
            #pragma unroll
            for (int nt = 0; nt < 4; nt++) {
                const int c = h * 128 + n1 + nt * 8 + tg * 2;
                const float b0 = eb1f[c], b1 = eb1f[c + 1];
                const float v0 = fmaxf(acc1[h][mi][nt][0] + b0, 0.f);
                const float v1 = fmaxf(acc1[h][mi][nt][1] + b1, 0.f);
                const float v2 = fmaxf(acc1[h][mi][nt][2] + b0, 0.f);
                const float v3 = fmaxf(acc1[h][mi][nt][3] + b1, 0.f);
                __nv_bfloat16* r0p = A2 + (size_t)r0 * KS2;
                __nv_bfloat16* r1p = A2 + (size_t)(r0 + 8) * KS2;
                split_store(r0p + c, r0p + 256 + c, v0, v1);
                split_store(r1p + c, r1p + 256 + c, v2, v3);
            }
        }
    }
    CP_WAIT0();
    __syncthreads();

    // ---- GEMM2: two 64-n halves; warp tile 32m x 32n (ldmatrix frags) ----
    const int m2 = (wid >> 1) * 32;
    const int n2 = (wid & 1) * 32;
    uint32_t aAddr2[2], bAddr2[2];
    #pragma unroll
    for (int mi = 0; mi < 2; mi++)
        aAddr2[mi] = sA2 + ((m2 + mi * 16 + lr + lq * 8) * KS2 + lh * 8) * 2;
    #pragma unroll
    for (int grp = 0; grp < 2; grp++)
        bAddr2[grp] = sB2 + ((n2 + grp * 16 + lh * 8 + lr) * KS2 + lq * 8) * 2;

    #pragma unroll 1
    for (int h2 = 0; h2 < 2; h2++) {
        float acc2[2][4][4] = {};
        #pragma unroll 1
        for (int seg = 0; seg < 3; seg++) {
            const int aofs = ((seg == 1) ? 256 : 0) * 2;
            const int bofs = ((seg == 2) ? 256 : 0) * 2;
            #pragma unroll 2
            for (int k16 = 0; k16 < 16; k16++) {
                const int ka = aofs + k16 * 32;
                const int kb = bofs + k16 * 32;
                uint32_t a[2][4], bb[2][4];
                #pragma unroll
                for (int mi = 0; mi < 2; mi++)
                    ldsm4(a[mi][0], a[mi][1], a[mi][2], a[mi][3], aAddr2[mi] + ka);
                #pragma unroll
                for (int j = 0; j < 2; j++)
                    ldsm4(bb[j][0], bb[j][1], bb[j][2], bb[j][3], bAddr2[j] + kb);
                #pragma unroll
                for (int nt = 0; nt < 4; nt++) {
                    const uint32_t* bp = (nt & 1) ? &bb[nt >> 1][2] : &bb[nt >> 1][0];
                    mma16816(acc2[0][nt], a[0], bp);
                    mma16816(acc2[1][nt], a[1], bp);
                }
            }
        }
        __syncthreads();   // GEMM2 half reads done; B2 buffer reusable

        if (h2 == 0) {     // prefetch B2 half 1 — overlaps scatter of half 0
            const float4* src = (const float4*)(g_B2bf + (size_t)64 * KS2);
            #pragma unroll 1
            for (int i = t; i < 4160; i += 256)
                cp16(sB2 + i * 16, src + i);
            CP_COMMIT();
        }

        // scatter in 2 phases of 64 m-rows (phase pg == batch pg)
        #pragma unroll 1
        for (int pg = 0; pg < 2; pg++) {
            if ((wid >> 1) == pg * 2 || (wid >> 1) == pg * 2 + 1) { /* warps with m2 in phase */ }
            if (m2 >> 6 == pg) {     // warps owning m in [pg*64, pg*64+64)
                #pragma unroll
                for (int mi = 0; mi < 2; mi++) {
                    const int r = m2 + mi * 16 + g - pg * 64;
                    #pragma unroll
                    for (int nt = 0; nt < 4; nt++) {
                        const int cc = n2 + nt * 8 + tg * 2;
                        const float b0 = eb2f[h2 * 64 + cc];
                        const float b1 = eb2f[h2 * 64 + cc + 1];
                        float2 lo, hi;
                        lo.x = acc2[mi][nt][0] + b0;
                        lo.y = acc2[mi][nt][1] + b1;
                        hi.x = acc2[mi][nt][2] + b0;
                        hi.y = acc2[mi][nt][3] + b1;
                        *(float2*)&Dh[r * DHS + cc]       = lo;
                        *(float2*)&Dh[(r + 8) * DHS + cc] = hi;
                    }
                }
            }
            __syncthreads();
            float* Hb = g_H + (size_t)pg * NNODE * OUT;
            #pragma unroll 1
            for (int i = t; i < 1024; i += 256) {
                const int r  = i >> 4;
                const int c4 = (i & 15) * 4;
                if (r < count) {
                    const float4 vv = *(const float4*)&Dh[r * DHS + c4];
                    red_add_v4(&Hb[(size_t)us[r] * OUT + h2 * 64 + c4], vv.x, vv.y, vv.z, vv.w);
                    red_add_v4(&Hb[(size_t)vs[r] * OUT + h2 * 64 + c4], vv.x, vv.y, vv.z, vv.w);
                }
            }
            __syncthreads();
        }
        if (h2 == 0) { CP_WAIT0(); __syncthreads(); }
    }
}

// ---------------------------------------------------------------------------
// Node MLP (fp32, R7 proven)
// ---------------------------------------------------------------------------
__global__ __launch_bounds__(256, 3) void node_mlp_kernel(
    const float* __restrict__ x,
    const float* __restrict__ nw1, const float* __restrict__ nb1,
    const float* __restrict__ nw2, const float* __restrict__ nb2)
{
    extern __shared__ float sm[];
    float* xsT = sm;
    float* hs  = sm + IN_DIM * RS;
    float* ws  = hs + MPB * HS_RS;

    const int t    = threadIdx.x;
    const int base = blockIdx.x * MPB;

    #pragma unroll
    for (int i = 0; i < 2; i++) {
        const int q  = t + i * 256;
        const int m  = q >> 4;
        const int c4 = (q & 15) * 4;
        const float4 v = *(const float4*)&x[(size_t)(base + m) * IN_DIM + c4];
        xsT[(c4 + 0) * RS + m] = v.x;
        xsT[(c4 + 1) * RS + m] = v.y;
        xsT[(c4 + 2) * RS + m] = v.z;
        xsT[(c4 + 3) * RS + m] = v.w;
    }

    {
        const int m0 = (t >> 6) * 8;
        const int n0 = (t & 63) * 4;
        const float4 b1 = *(const float4*)&nb1[n0];
        float acc[8][4];
        #pragma unroll
        for (int i = 0; i < 8; i++) {
            acc[i][0] = b1.x; acc[i][1] = b1.y; acc[i][2] = b1.z; acc[i][3] = b1.w;
        }
        #pragma unroll 1
        for (int kc = 0; kc < IN_DIM / 16; kc++) {
            __syncthreads();
            {
                const float4* src = (const float4*)(nw1 + kc * 16 * HID);
                float4* dst = (float4*)ws;
                #pragma unroll
                for (int j = 0; j < 4; j++) dst[t + j * 256] = src[t + j * 256];
            }
            __syncthreads();
            const float* aT = xsT + kc * 16 * RS;
            #pragma unroll 4
            for (int k = 0; k < 16; k++) {
                const float4 bv = *(const float4*)&ws[k * HID + n0];
                const float4 a0 = *(const float4*)&aT[k * RS + m0];
                const float4 a1 = *(const float4*)&aT[k * RS + m0 + 4];
                acc[0][0] = fmaf(a0.x, bv.x, acc[0][0]); acc[0][1] = fmaf(a0.x, bv.y, acc[0][1]);
                acc[0][2] = fmaf(a0.x, bv.z, acc[0][2]); acc[0][3] = fmaf(a0.x, bv.w, acc[0][3]);
                acc[1][0] = fmaf(a0.y, bv.x, acc[1][0]); acc[1][1] = fmaf(a0.y, bv.y, acc[1][1]);
                acc[1][2] = fmaf(a0.y, bv.z, acc[1][2]); acc[1][3] = fmaf(a0.y, bv.w, acc[1][3]);
                acc[2][0] = fmaf(a0.z, bv.x, acc[2][0]); acc[2][1] = fmaf(a0.z, bv.y, acc[2][1]);
                acc[2][2] = fmaf(a0.z, bv.z, acc[2][2]); acc[2][3] = fmaf(a0.z, bv.w, acc[2][3]);
                acc[3][0] = fmaf(a0.w, bv.x, acc[3][0]); acc[3][1] = fmaf(a0.w, bv.y, acc[3][1]);
                acc[3][2] = fmaf(a0.w, bv.z, acc[3][2]); acc[3][3] = fmaf(a0.w, bv.w, acc[3][3]);
                acc[4][0] = fmaf(a1.x, bv.x, acc[4][0]); acc[4][1] = fmaf(a1.x, bv.y, acc[4][1]);
                acc[4][2] = fmaf(a1.x, bv.z, acc[4][2]); acc[4][3] = fmaf(a1.x, bv.w, acc[4][3]);
                acc[5][0] = fmaf(a1.y, bv.x, acc[5][0]); acc[5][1] = fmaf(a1.y, bv.y, acc[5][1]);
                acc[5][2] = fmaf(a1.y, bv.z, acc[5][2]); acc[5][3] = fmaf(a1.y, bv.w, acc[5][3]);
                acc[6][0] = fmaf(a1.z, bv.x, acc[6][0]); acc[6][1] = fmaf(a1.z, bv.y, acc[6][1]);
                acc[6][2] = fmaf(a1.z, bv.z, acc[6][2]); acc[6][3] = fmaf(a1.z, bv.w, acc[6][3]);
                acc[7][0] = fmaf(a1.w, bv.x, acc[7][0]); acc[7][1] = fmaf(a1.w, bv.y, acc[7][1]);
                acc[7][2] = fmaf(a1.w, bv.z, acc[7][2]); acc[7][3] = fmaf(a1.w, bv.w, acc[7][3]);
            }
        }
        #pragma unroll
        for (int i = 0; i < 8; i++) {
            float4 r = make_float4(fmaxf(acc[i][0], 0.f), fmaxf(acc[i][1], 0.f),
                                   fmaxf(acc[i][2], 0.f), fmaxf(acc[i][3], 0.f));
            *(float4*)&hs[(m0 + i) * HS_RS + n0] = r;
        }
    }

    {
        const int m0 = (t >> 5) * 4;
        const int n0 = (t & 31) * 4;
        const float4 b2 = *(const float4*)&nb2[n0];
        float acc[4][4];
        #pragma unroll
        for (int i = 0; i < 4; i++) {
            acc[i][0] = b2.x; acc[i][1] = b2.y; acc[i][2] = b2.z; acc[i][3] = b2.w;
        }
        #pragma unroll 1
        for (int kc = 0; kc < HID / 32; kc++) {
            __syncthreads();
            {
                const float4* src = (const float4*)(nw2 + kc * 32 * OUT);
                float4* dst = (float4*)ws;
                #pragma unroll
                for (int j = 0; j < 4; j++) dst[t + j * 256] = src[t + j * 256];
            }
            __syncthreads();
            #pragma unroll 2
            for (int k4 = 0; k4 < 32; k4 += 4) {
                const float4 b0  = *(const float4*)&ws[(k4 + 0) * OUT + n0];
                const float4 b1v = *(const float4*)&ws[(k4 + 1) * OUT + n0];
                const float4 b2v = *(const float4*)&ws[(k4 + 2) * OUT + n0];
                const float4 b3v = *(const float4*)&ws[(k4 + 3) * OUT + n0];
                #pragma unroll
                for (int i = 0; i < 4; i++) {
                    const float4 a = *(const float4*)&hs[(m0 + i) * HS_RS + kc * 32 + k4];
                    acc[i][0] = fmaf(a.x, b0.x,  acc[i][0]);
                    acc[i][1] = fmaf(a.x, b0.y,  acc[i][1]);
                    acc[i][2] = fmaf(a.x, b0.z,  acc[i][2]);
                    acc[i][3] = fmaf(a.x, b0.w,  acc[i][3]);
                    acc[i][0] = fmaf(a.y, b1v.x, acc[i][0]);
                    acc[i][1] = fmaf(a.y, b1v.y, acc[i][1]);
                    acc[i][2] = fmaf(a.y, b1v.z, acc[i][2]);
                    acc[i][3] = fmaf(a.y, b1v.w, acc[i][3]);
                    acc[i][0] = fmaf(a.z, b2v.x, acc[i][0]);
                    acc[i][1] = fmaf(a.z, b2v.y, acc[i][1]);
                    acc[i][2] = fmaf(a.z, b2v.z, acc[i][2]);
                    acc[i][3] = fmaf(a.z, b2v.w, acc[i][3]);
                    acc[i][0] = fmaf(a.w, b3v.x, acc[i][0]);
                    acc[i][1] = fmaf(a.w, b3v.y, acc[i][1]);
                    acc[i][2] = fmaf(a.w, b3v.z, acc[i][2]);
                    acc[i][3] = fmaf(a.w, b3v.w, acc[i][3]);
                }
            }
        }
        #pragma unroll
        for (int i = 0; i < 4; i++)
            *(float4*)&g_H[(size_t)(base + m0 + i) * OUT + n0] =
                make_float4(acc[i][0], acc[i][1], acc[i][2], acc[i][3]);
    }
}

// ---------------------------------------------------------------------------
// decode: out = H @ dw + db (unchanged)
// ---------------------------------------------------------------------------
__global__ __launch_bounds__(256) void decode_kernel(
    const float* __restrict__ dw, const float* __restrict__ db,
    float* __restrict__ out)
{
    __shared__ __align__(16) float hsm[DPB][OUT];

    const int base = blockIdx.x * DPB;
    const int t = threadIdx.x;

    for (int i = t; i < DPB * OUT; i += 256)
        hsm[i / OUT][i % OUT] = g_H[(size_t)base * OUT + i];
    __syncthreads();

    const int o   = t & (IN_DIM - 1);
    const int nb0 = (t >> 6) * (DPB / 4);
    float acc[DPB / 4];
    {
        const float bb = db[o];
        #pragma unroll
        for (int n = 0; n < DPB / 4; n++) acc[n] = bb;
    }
    #pragma unroll 4
    for (int k = 0; k < OUT; k += 4) {
        const float w0 = dw[(k + 0) * IN_DIM + o];
        const float w1 = dw[(k + 1) * IN_DIM + o];
        const float w2 = dw[(k + 2) * IN_DIM + o];
        const float w3 = dw[(k + 3) * IN_DIM + o];
        #pragma unroll
        for (int n = 0; n < DPB / 4; n++) {
            float4 v = *reinterpret_cast<const float4*>(&hsm[nb0 + n][k]);
            acc[n] = fmaf(v.x, w0, acc[n]);
            acc[n] = fmaf(v.y, w1, acc[n]);
            acc[n] = fmaf(v.z, w2, acc[n]);
            acc[n] = fmaf(v.w, w3, acc[n]);
        }
    }
    #pragma unroll
    for (int n = 0; n < DPB / 4; n++)
        out[(size_t)(base + nb0 + n) * IN_DIM + o] = acc[n];
}

// ---------------------------------------------------------------------------
extern "C" void kernel_launch(void* const* d_in, const int* in_sizes, int n_in,
                              void* d_out, int out_size)
{
    const float* x   = (const float*)d_in[0];
    const int*   e32 = (const int*)d_in[1];
    const float* ew1 = (const float*)d_in[2];
    const float* eb1 = (const float*)d_in[3];
    const float* ew2 = (const float*)d_in[4];
    const float* eb2 = (const float*)d_in[5];
    const float* nw1 = (const float*)d_in[6];
    const float* nb1 = (const float*)d_in[7];
    const float* nw2 = (const float*)d_in[8];
    const float* nb2 = (const float*)d_in[9];
    const float* dw  = (const float*)d_in[10];
    const float* db  = (const float*)d_in[11];
    float*       out = (float*)d_out;

    const int node_smem = (IN_DIM * RS + MPB * HS_RS + 16 * HID) * (int)sizeof(float); // 58880

    static bool attr_done = false;
    if (!attr_done) {
        cudaFuncSetAttribute(edge_mlp_tc_kernel,
            cudaFuncAttributeMaxDynamicSharedMemorySize, EDGE_DSMEM);
        cudaFuncSetAttribute(node_mlp_kernel,
            cudaFuncAttributeMaxDynamicSharedMemorySize, node_smem);
        attr_done = true;
    }

    detect_edge_dtype_kernel<<<1, 32>>>(e32);
    convert_edges_kernel<<<(NEDGE + 255) / 256, 256>>>(e32);
    prep_weights_kernel<<<128, 256>>>(ew1, ew2);

    node_mlp_kernel<<<TOTAL_NODES / MPB, 256, node_smem>>>(x, nw1, nb1, nw2, nb2);

    edge_mlp_tc_kernel<<<(NEDGE + 63) / 64, 256, EDGE_DSMEM>>>(x, eb1, eb2);

    decode_kernel<<<TOTAL_NODES / DPB, 256>>>(dw, db, out);
}

// round 14
// speedup vs baseline: 1.0759x; 1.0759x over previous
#include <cuda_runtime.h>
#include <cuda_bf16.h>
#include <cstdint>

#define B      2
#define NNODE  50000
#define IN_DIM 64
#define HID    256
#define OUT    128
#define NEDGE  500000
#define TOTAL_NODES (B * NNODE)
#define DPB 16

// tensor kernels
#define KS1  264     // edge A1/B1 row stride (bf16): 128 hi + 128 lo + 8 pad
#define KN1  136     // node A1/B1 + all B2-chunk row stride (bf16): 128 + 8 pad
#define KS2  520     // A2 row stride (bf16): 256 hi + 256 lo + 8 pad
#define DHS2 132     // Dh row stride (f32)
#define CHB  34816   // one B2 chunk: 128*136*2 bytes

// edge smem layout (bytes)
#define EOFF_A1  0        // 128*264*2 = 67584
#define EOFF_B1  67584    // 256*264*2 = 135168 -> ends 202752
#define EOFF_A2  0        // 128*520*2 = 133120 (overlays A1+B1 after GEMM1)
#define EOFF_B2  133120   // 2 chunks  = 69632  -> ends 202752
#define EOFF_DH  133120   // 64*132*4  = 33792 (after GEMM2 done, B2 dead)
#define EDGE_DSMEM 202752

// node smem layout (bytes)
#define NOFF_A1  0        // 128*136*2 = 34816
#define NOFF_B1  34816    // 256*136*2 = 69632 -> ends 104448
#define NOFF_A2  0        // 133120
#define NOFF_B2  133120   // 69632 -> ends 202752
#define NOFF_DH  133120
#define NODE_DSMEM 202752

// ---------------------------------------------------------------------------
// device globals (allocation-guard-safe)
// ---------------------------------------------------------------------------
__device__ float g_H[(size_t)B * NNODE * OUT];
__device__ int   g_eu[NEDGE];
__device__ int   g_ev[NEDGE];
__device__ int   g_is64;
__device__ __align__(16) __nv_bfloat16 g_B1bf[256 * KS1];   // edge ew1 image
__device__ __align__(16) __nv_bfloat16 g_B2ch[4 * 128 * KN1]; // edge ew2 chunks
__device__ __align__(16) __nv_bfloat16 g_NB1bf[256 * KN1];  // node nw1 image
__device__ __align__(16) __nv_bfloat16 g_NB2ch[4 * 128 * KN1]; // node nw2 chunks

// ---------------------------------------------------------------------------
// helpers
// ---------------------------------------------------------------------------
static __device__ __forceinline__ void mma16816(float* d, const uint32_t* a, const uint32_t* b)
{
    asm volatile(
        "mma.sync.aligned.m16n8k16.row.col.f32.bf16.bf16.f32 "
        "{%0,%1,%2,%3}, {%4,%5,%6,%7}, {%8,%9}, {%0,%1,%2,%3};"
        : "+f"(d[0]), "+f"(d[1]), "+f"(d[2]), "+f"(d[3])
        : "r"(a[0]), "r"(a[1]), "r"(a[2]), "r"(a[3]), "r"(b[0]), "r"(b[1]));
}

static __device__ __forceinline__ void ldsm4(uint32_t& r0, uint32_t& r1, uint32_t& r2,
                                             uint32_t& r3, uint32_t addr)
{
    asm volatile("ldmatrix.sync.aligned.m8n8.x4.shared.b16 {%0,%1,%2,%3}, [%4];"
                 : "=r"(r0), "=r"(r1), "=r"(r2), "=r"(r3) : "r"(addr));
}

static __device__ __forceinline__ void cp16(uint32_t dst, const void* src)
{
    asm volatile("cp.async.cg.shared.global [%0], [%1], 16;" :: "r"(dst), "l"(src) : "memory");
}
#define CP_COMMIT() asm volatile("cp.async.commit_group;" ::: "memory")
#define CP_WAIT0()  asm volatile("cp.async.wait_group 0;" ::: "memory")

static __device__ __forceinline__ void red_add_v4(float* p, float a, float b, float c, float d)
{
    asm volatile("red.global.add.v4.f32 [%0], {%1, %2, %3, %4};"
                 :: "l"(p), "f"(a), "f"(b), "f"(c), "f"(d) : "memory");
}

static __device__ __forceinline__ void split_store(__nv_bfloat16* hi_p, __nv_bfloat16* lo_p,
                                                   float v0, float v1)
{
    __nv_bfloat162 hp = __floats2bfloat162_rn(v0, v1);
    const float h0 = __bfloat162float(hp.x), h1 = __bfloat162float(hp.y);
    __nv_bfloat162 lp = __floats2bfloat162_rn(v0 - h0, v1 - h1);
    *(uint32_t*)hi_p = *(const uint32_t*)&hp;
    *(uint32_t*)lo_p = *(const uint32_t*)&lp;
}

// ---------------------------------------------------------------------------
// edge dtype detect + SoA normalize (proven)
// ---------------------------------------------------------------------------
__global__ void detect_edge_dtype_kernel(const int* __restrict__ e32)
{
    if (threadIdx.x == 0 && blockIdx.x == 0) {
        int all_zero = 1;
        #pragma unroll 1
        for (int i = 1; i < 256; i += 2)
            if (e32[i] != 0) { all_zero = 0; break; }
        g_is64 = all_zero;
    }
}

__global__ __launch_bounds__(256) void convert_edges_kernel(const int* __restrict__ e32)
{
    const int e = blockIdx.x * 256 + threadIdx.x;
    if (e < NEDGE) {
        if (g_is64) { g_eu[e] = e32[4 * e + 0]; g_ev[e] = e32[4 * e + 2]; }
        else        { g_eu[e] = e32[2 * e + 0]; g_ev[e] = e32[2 * e + 1]; }
    }
}

// ---------------------------------------------------------------------------
// weight prep: split fp32 -> bf16 hi/lo images
// ---------------------------------------------------------------------------
__global__ __launch_bounds__(256) void prep_weights_kernel(
    const float* __restrict__ ew1, const float* __restrict__ ew2,
    const float* __restrict__ nw1, const float* __restrict__ nw2)
{
    const int tid = blockIdx.x * 256 + threadIdx.x;
    const int stride = gridDim.x * 256;
    // edge B1 [256n][128hi|128lo]
    for (int idx = tid; idx < 256 * 128; idx += stride) {
        const int n = idx >> 7, k = idx & 127;
        const float w = ew1[k * HID + n];
        const __nv_bfloat16 hi = __float2bfloat16_rn(w);
        g_B1bf[n * KS1 + k]       = hi;
        g_B1bf[n * KS1 + 128 + k] = __float2bfloat16_rn(w - __bfloat162float(hi));
    }
    // edge B2 chunks: c0/c1 = hi(k 0-127 / 128-255), c2/c3 = lo
    for (int idx = tid; idx < 4 * 128 * 128; idx += stride) {
        const int c = idx >> 14;
        const int r = idx & 16383;
        const int n = r >> 7, l = r & 127;
        const int k = (c & 1) * 128 + l;
        const float w = ew2[k * OUT + n];
        const __nv_bfloat16 hi = __float2bfloat16_rn(w);
        g_B2ch[(c * 128 + n) * KN1 + l] =
            (c < 2) ? hi : __float2bfloat16_rn(w - __bfloat162float(hi));
    }
    // node B1 [256n][64hi|64lo]
    for (int idx = tid; idx < 256 * 64; idx += stride) {
        const int n = idx >> 6, k = idx & 63;
        const float w = nw1[k * HID + n];
        const __nv_bfloat16 hi = __float2bfloat16_rn(w);
        g_NB1bf[n * KN1 + k]      = hi;
        g_NB1bf[n * KN1 + 64 + k] = __float2bfloat16_rn(w - __bfloat162float(hi));
    }
    // node B2 chunks (nw2)
    for (int idx = tid; idx < 4 * 128 * 128; idx += stride) {
        const int c = idx >> 14;
        const int r = idx & 16383;
        const int n = r >> 7, l = r & 127;
        const int k = (c & 1) * 128 + l;
        const float w = nw2[k * OUT + n];
        const __nv_bfloat16 hi = __float2bfloat16_rn(w);
        g_NB2ch[(c * 128 + n) * KN1 + l] =
            (c < 2) ? hi : __float2bfloat16_rn(w - __bfloat162float(hi));
    }
}

// ---------------------------------------------------------------------------
// shared GEMM2: A2[128m x 512k'] @ chunked B2 -> acc2[4mi][4nt][4]
// warp tile 64m x 32n over full N=128; B2 double-buffered k-chunks.
// ---------------------------------------------------------------------------
static __device__ __forceinline__ void gemm2_chunked(
    float (*acc2)[4][4], const __nv_bfloat16* gB2ch,
    uint32_t sA2, uint32_t sB2, int m2, int n2t,
    int t, int lr, int lq, int lh)
{
    uint32_t aA2[4];
    #pragma unroll
    for (int mi = 0; mi < 4; mi++)
        aA2[mi] = sA2 + ((m2 + mi * 16 + lr + lq * 8) * KS2 + lh * 8) * 2;

    const int ABASE0[4] = {0, 128, 0, 128};
    const int ABASE1[2] = {256, 384};

    #pragma unroll 1
    for (int c = 0; c < 4; c++) {
        CP_WAIT0();
        __syncthreads();
        if (c < 3) {
            const float4* src = (const float4*)(gB2ch + (size_t)(c + 1) * 128 * KN1);
            const uint32_t dst = sB2 + ((c + 1) & 1) * CHB;
            #pragma unroll 1
            for (int i = t; i < 2176; i += 256) cp16(dst + i * 16, src + i);
            CP_COMMIT();
        }
        const uint32_t sBc = sB2 + (c & 1) * CHB;
        uint32_t bA[2];
        #pragma unroll
        for (int grp = 0; grp < 2; grp++)
            bA[grp] = sBc + ((n2t + grp * 16 + lh * 8 + lr) * KN1 + lq * 8) * 2;

        const int npass = (c < 2) ? 2 : 1;
        #pragma unroll 1
        for (int p = 0; p < npass; p++) {
            const int ab = (p == 0) ? ABASE0[c] : ABASE1[c];
            #pragma unroll 2
            for (int k16 = 0; k16 < 8; k16++) {
                const int ka = (ab + k16 * 16) * 2;
                const int kb = k16 * 32;
                uint32_t a[4][4], bb[2][4];
                #pragma unroll
                for (int mi = 0; mi < 4; mi++)
                    ldsm4(a[mi][0], a[mi][1], a[mi][2], a[mi][3], aA2[mi] + ka);
                #pragma unroll
                for (int j = 0; j < 2; j++)
                    ldsm4(bb[j][0], bb[j][1], bb[j][2], bb[j][3], bA[j] + kb);
                #pragma unroll
                for (int nt = 0; nt < 4; nt++) {
                    const uint32_t* bp = (nt & 1) ? &bb[nt >> 1][2] : &bb[nt >> 1][0];
                    #pragma unroll
                    for (int mi = 0; mi < 4; mi++)
                        mma16816(acc2[mi][nt], a[mi], bp);
                }
            }
        }
    }
    __syncthreads();   // all MMAs done; B2 buffers dead (Dh overlays them)
}

// ---------------------------------------------------------------------------
// Edge MLP v9
// ---------------------------------------------------------------------------
__global__ __launch_bounds__(256, 1) void edge_mlp_tc_kernel(
    const float* __restrict__ x,
    const float* __restrict__ eb1, const float* __restrict__ eb2)
{
    extern __shared__ __align__(16) char smc[];
    __nv_bfloat16* A1 = (__nv_bfloat16*)(smc + EOFF_A1);
    __nv_bfloat16* B1 = (__nv_bfloat16*)(smc + EOFF_B1);
    __nv_bfloat16* A2 = (__nv_bfloat16*)(smc + EOFF_A2);
    float*         Dh = (float*)(smc + EOFF_DH);

    __shared__ int   us[64], vs[64];
    __shared__ float eb1f[HID], eb2f[OUT];

    const int t   = threadIdx.x;
    const int wid = t >> 5;
    const int lid = t & 31;
    const int g   = lid >> 2;
    const int tg  = lid & 3;
    const int lr  = lid & 7;
    const int lq  = (lid >> 3) & 1;
    const int lh  = lid >> 4;
    const int e0  = blockIdx.x * 64;
    const int count = min(64, NEDGE - e0);

    const uint32_t sA1 = (uint32_t)__cvta_generic_to_shared(A1);
    const uint32_t sB1 = (uint32_t)__cvta_generic_to_shared(B1);
    const uint32_t sA2 = (uint32_t)__cvta_generic_to_shared(A2);
    const uint32_t sB2 = (uint32_t)__cvta_generic_to_shared(smc + EOFF_B2);

    if (t < 64) {
        const int e = min(e0 + t, NEDGE - 1);
        us[t] = g_eu[e]; vs[t] = g_ev[e];
    }
    eb1f[t] = eb1[t];
    if (t < OUT) eb2f[t] = eb2[t];

    {   // prefetch B1 (135168 B) — overlaps gather
        const float4* src = (const float4*)g_B1bf;
        #pragma unroll 1
        for (int i = t; i < 8448; i += 256) cp16(sB1 + i * 16, src + i);
        CP_COMMIT();
    }
    __syncthreads();

    // gather: rows 0-63 batch0, 64-127 batch1
    #pragma unroll
    for (int it = 0; it < 32; it++) {
        const int q = t + it * 256;
        const int m = q >> 6;
        const int c = (q & 63) * 2;
        const int node = (c < IN_DIM) ? us[m & 63] : vs[m & 63];
        const float2 xv = *(const float2*)
            &x[((size_t)(m >> 6) * NNODE + node) * IN_DIM + (c & (IN_DIM - 1))];
        split_store(A1 + m * KS1 + c, A1 + m * KS1 + 128 + c, xv.x, xv.y);
    }
    CP_WAIT0();
    __syncthreads();

    // ---- GEMM1 (unchanged): warp tile 64m x 32n, 2 n-halves ----
    const int m1 = (wid >> 2) * 64;
    const int n1 = (wid & 3) * 32;
    uint32_t aAddr1[4], bAddr1[4];
    #pragma unroll
    for (int mi = 0; mi < 4; mi++)
        aAddr1[mi] = sA1 + ((m1 + mi * 16 + lr + lq * 8) * KS1 + lh * 8) * 2;
    #pragma unroll
    for (int h = 0; h < 2; h++)
        #pragma unroll
        for (int grp = 0; grp < 2; grp++)
            bAddr1[h * 2 + grp] = sB1 + ((h * 128 + n1 + grp * 16 + lh * 8 + lr) * KS1 + lq * 8) * 2;

    float acc1[2][4][4][4] = {};
    #pragma unroll 1
    for (int seg = 0; seg < 3; seg++) {
        const int aofs = ((seg == 1) ? 128 : 0) * 2;
        const int bofs = ((seg == 2) ? 128 : 0) * 2;
        #pragma unroll 2
        for (int k16 = 0; k16 < 8; k16++) {
            const int ka = aofs + k16 * 32;
            const int kb = bofs + k16 * 32;
            uint32_t a[4][4], bb[4][4];
            #pragma unroll
            for (int mi = 0; mi < 4; mi++)
                ldsm4(a[mi][0], a[mi][1], a[mi][2], a[mi][3], aAddr1[mi] + ka);
            #pragma unroll
            for (int j = 0; j < 4; j++)
                ldsm4(bb[j][0], bb[j][1], bb[j][2], bb[j][3], bAddr1[j] + kb);
            #pragma unroll
            for (int h = 0; h < 2; h++)
                #pragma unroll
                for (int nt = 0; nt < 4; nt++) {
                    const uint32_t* bp = (nt & 1) ? &bb[h * 2 + (nt >> 1)][2]
                                                  : &bb[h * 2 + (nt >> 1)][0];
                    #pragma unroll
                    for (int mi = 0; mi < 4; mi++)
                        mma16816(acc1[h][mi][nt], a[mi], bp);
                }
        }
    }
    __syncthreads();

    {   // prefetch B2 chunk0 (region = dead B1 tail)
        const float4* src = (const float4*)g_B2ch;
        #pragma unroll 1
        for (int i = t; i < 2176; i += 256) cp16(sB2 + i * 16, src + i);
        CP_COMMIT();
    }

    // epilogue G1 -> A2 (overlaps chunk0 prefetch)
    #pragma unroll
    for (int h = 0; h < 2; h++)
        #pragma unroll
        for (int mi = 0; mi < 4; mi++) {
            const int r0 = m1 + mi * 16 + g;
            #pragma unroll
            for (int nt = 0; nt < 4; nt++) {
                const int c = h * 128 + n1 + nt * 8 + tg * 2;
                const float b0 = eb1f[c], b1 = eb1f[c + 1];
                const float v0 = fmaxf(acc1[h][mi][nt][0] + b0, 0.f);
                const float v1 = fmaxf(acc1[h][mi][nt][1] + b1, 0.f);
                const float v2 = fmaxf(acc1[h][mi][nt][2] + b0, 0.f);
                const float v3 = fmaxf(acc1[h][mi][nt][3] + b1, 0.f);
                __nv_bfloat16* r0p = A2 + (size_t)r0 * KS2;
                __nv_bfloat16* r1p = A2 + (size_t)(r0 + 8) * KS2;
                split_store(r0p + c, r0p + 256 + c, v0, v1);
                split_store(r1p + c, r1p + 256 + c, v2, v3);
            }
        }

    // ---- GEMM2 chunked ----
    const int m2  = (wid >> 2) * 64;
    const int n2t = (wid & 3) * 32;
    float acc2[4][4][4] = {};
    gemm2_chunked(acc2, g_B2ch, sA2, sB2, m2, n2t, t, lr, lq, lh);

    // ---- epilogue + scatter, phased by batch (pg == m2>>6 owner) ----
    #pragma unroll 1
    for (int pg = 0; pg < 2; pg++) {
        if ((m2 >> 6) == pg) {
            #pragma unroll
            for (int mi = 0; mi < 4; mi++) {
                const int r = (m2 - pg * 64) + mi * 16 + g;
                #pragma unroll
                for (int nt = 0; nt < 4; nt++) {
                    const int cc = n2t + nt * 8 + tg * 2;
                    const float b0 = eb2f[cc], b1 = eb2f[cc + 1];
                    float2 lo, hi;
                    lo.x = acc2[mi][nt][0] + b0;
                    lo.y = acc2[mi][nt][1] + b1;
                    hi.x = acc2[mi][nt][2] + b0;
                    hi.y = acc2[mi][nt][3] + b1;
                    *(float2*)&Dh[r * DHS2 + cc]       = lo;
                    *(float2*)&Dh[(r + 8) * DHS2 + cc] = hi;
                }
            }
        }
        __syncthreads();
        float* Hb = g_H + (size_t)pg * NNODE * OUT;
        #pragma unroll 1
        for (int i = t; i < 2048; i += 256) {
            const int r  = i >> 5;
            const int c4 = (i & 31) * 4;
            if (r < count) {
                const float4 vv = *(const float4*)&Dh[r * DHS2 + c4];
                red_add_v4(&Hb[(size_t)us[r] * OUT + c4], vv.x, vv.y, vv.z, vv.w);
                red_add_v4(&Hb[(size_t)vs[r] * OUT + c4], vv.x, vv.y, vv.z, vv.w);
            }
        }
        __syncthreads();
    }
}

// ---------------------------------------------------------------------------
// Node MLP v9 (tensor): 128 nodes/block, split-bf16, plain stores
// ---------------------------------------------------------------------------
__global__ __launch_bounds__(256, 1) void node_mlp_tc_kernel(
    const float* __restrict__ x,
    const float* __restrict__ nb1, const float* __restrict__ nb2)
{
    extern __shared__ __align__(16) char smc[];
    __nv_bfloat16* A1 = (__nv_bfloat16*)(smc + NOFF_A1);
    __nv_bfloat16* B1 = (__nv_bfloat16*)(smc + NOFF_B1);
    __nv_bfloat16* A2 = (__nv_bfloat16*)(smc + NOFF_A2);
    float*         Dh = (float*)(smc + NOFF_DH);

    __shared__ float nb1f[HID], nb2f[OUT];

    const int t   = threadIdx.x;
    const int wid = t >> 5;
    const int lid = t & 31;
    const int g   = lid >> 2;
    const int tg  = lid & 3;
    const int lr  = lid & 7;
    const int lq  = (lid >> 3) & 1;
    const int lh  = lid >> 4;
    const int base = blockIdx.x * 128;

    const uint32_t sA1 = (uint32_t)__cvta_generic_to_shared(A1);
    const uint32_t sB1 = (uint32_t)__cvta_generic_to_shared(B1);
    const uint32_t sA2 = (uint32_t)__cvta_generic_to_shared(A2);
    const uint32_t sB2 = (uint32_t)__cvta_generic_to_shared(smc + NOFF_B2);

    nb1f[t] = nb1[t];
    if (t < OUT) nb2f[t] = nb2[t];

    {   // prefetch B1 (69632 B) — overlaps A load
        const float4* src = (const float4*)g_NB1bf;
        #pragma unroll 1
        for (int i = t; i < 4352; i += 256) cp16(sB1 + i * 16, src + i);
        CP_COMMIT();
    }

    // load x rows (clamped), split hi|lo into A1 [128m][64hi|64lo]
    #pragma unroll
    for (int it = 0; it < 16; it++) {
        const int q = t + it * 256;              // 4096 float2
        const int m = q >> 5;
        const int c = (q & 31) * 2;
        const int row = min(base + m, TOTAL_NODES - 1);
        const float2 xv = *(const float2*)&x[(size_t)row * IN_DIM + c];
        split_store(A1 + m * KN1 + c, A1 + m * KN1 + 64 + c, xv.x, xv.y);
    }
    CP_WAIT0();
    __syncthreads();

    // ---- GEMM1: K=64 (3 segs x 4 k16), warp tile 64m x 32n, 2 n-halves ----
    const int m1 = (wid >> 2) * 64;
    const int n1 = (wid & 3) * 32;
    uint32_t aAddr1[4], bAddr1[4];
    #pragma unroll
    for (int mi = 0; mi < 4; mi++)
        aAddr1[mi] = sA1 + ((m1 + mi * 16 + lr + lq * 8) * KN1 + lh * 8) * 2;
    #pragma unroll
    for (int h = 0; h < 2; h++)
        #pragma unroll
        for (int grp = 0; grp < 2; grp++)
            bAddr1[h * 2 + grp] = sB1 + ((h * 128 + n1 + grp * 16 + lh * 8 + lr) * KN1 + lq * 8) * 2;

    float acc1[2][4][4][4] = {};
    #pragma unroll 1
    for (int seg = 0; seg < 3; seg++) {
        const int aofs = ((seg == 1) ? 64 : 0) * 2;
        const int bofs = ((seg == 2) ? 64 : 0) * 2;
        #pragma unroll
        for (int k16 = 0; k16 < 4; k16++) {
            const int ka = aofs + k16 * 32;
            const int kb = bofs + k16 * 32;
            uint32_t a[4][4], bb[4][4];
            #pragma unroll
            for (int mi = 0; mi < 4; mi++)
                ldsm4(a[mi][0], a[mi][1], a[mi][2], a[mi][3], aAddr1[mi] + ka);
            #pragma unroll
            for (int j = 0; j < 4; j++)
                ldsm4(bb[j][0], bb[j][1], bb[j][2], bb[j][3], bAddr1[j] + kb);
            #pragma unroll
            for (int h = 0; h < 2; h++)
                #pragma unroll
                for (int nt = 0; nt < 4; nt++) {
                    const uint32_t* bp = (nt & 1) ? &bb[h * 2 + (nt >> 1)][2]
                                                  : &bb[h * 2 + (nt >> 1)][0];
                    #pragma unroll
                    for (int mi = 0; mi < 4; mi++)
                        mma16816(acc1[h][mi][nt], a[mi], bp);
                }
        }
    }
    __syncthreads();

    {   // prefetch B2 chunk0
        const float4* src = (const float4*)g_NB2ch;
        #pragma unroll 1
        for (int i = t; i < 2176; i += 256) cp16(sB2 + i * 16, src + i);
        CP_COMMIT();
    }

    // epilogue G1 -> A2
    #pragma unroll
    for (int h = 0; h < 2; h++)
        #pragma unroll
        for (int mi = 0; mi < 4; mi++) {
            const int r0 = m1 + mi * 16 + g;
            #pragma unroll
            for (int nt = 0; nt < 4; nt++) {
                const int c = h * 128 + n1 + nt * 8 + tg * 2;
                const float b0 = nb1f[c], b1 = nb1f[c + 1];
                const float v0 = fmaxf(acc1[h][mi][nt][0] + b0, 0.f);
                const float v1 = fmaxf(acc1[h][mi][nt][1] + b1, 0.f);
                const float v2 = fmaxf(acc1[h][mi][nt][2] + b0, 0.f);
                const float v3 = fmaxf(acc1[h][mi][nt][3] + b1, 0.f);
                __nv_bfloat16* r0p = A2 + (size_t)r0 * KS2;
                __nv_bfloat16* r1p = A2 + (size_t)(r0 + 8) * KS2;
                split_store(r0p + c, r0p + 256 + c, v0, v1);
                split_store(r1p + c, r1p + 256 + c, v2, v3);
            }
        }

    // ---- GEMM2 chunked ----
    const int m2  = (wid >> 2) * 64;
    const int n2t = (wid & 3) * 32;
    float acc2[4][4][4] = {};
    gemm2_chunked(acc2, g_NB2ch, sA2, sB2, m2, n2t, t, lr, lq, lh);

    // ---- epilogue + store, phased in 64-row groups ----
    #pragma unroll 1
    for (int pg = 0; pg < 2; pg++) {
        if ((m2 >> 6) == pg) {
            #pragma unroll
            for (int mi = 0; mi < 4; mi++) {
                const int r = (m2 - pg * 64) + mi * 16 + g;
                #pragma unroll
                for (int nt = 0; nt < 4; nt++) {
                    const int cc = n2t + nt * 8 + tg * 2;
                    const float b0 = nb2f[cc], b1 = nb2f[cc + 1];
                    float2 lo, hi;
                    lo.x = acc2[mi][nt][0] + b0;
                    lo.y = acc2[mi][nt][1] + b1;
                    hi.x = acc2[mi][nt][2] + b0;
                    hi.y = acc2[mi][nt][3] + b1;
                    *(float2*)&Dh[r * DHS2 + cc]       = lo;
                    *(float2*)&Dh[(r + 8) * DHS2 + cc] = hi;
                }
            }
        }
        __syncthreads();
        #pragma unroll 1
        for (int i = t; i < 2048; i += 256) {
            const int r   = i >> 5;
            const int c4  = (i & 31) * 4;
            const int row = base + pg * 64 + r;
            if (row < TOTAL_NODES)
                *(float4*)&g_H[(size_t)row * OUT + c4] = *(const float4*)&Dh[r * DHS2 + c4];
        }
        __syncthreads();
    }
}

// ---------------------------------------------------------------------------
// decode: out = H @ dw + db (unchanged)
// ---------------------------------------------------------------------------
__global__ __launch_bounds__(256) void decode_kernel(
    const float* __restrict__ dw, const float* __restrict__ db,
    float* __restrict__ out)
{
    __shared__ __align__(16) float hsm[DPB][OUT];

    const int base = blockIdx.x * DPB;
    const int t = threadIdx.x;

    for (int i = t; i < DPB * OUT; i += 256)
        hsm[i / OUT][i % OUT] = g_H[(size_t)base * OUT + i];
    __syncthreads();

    const int o   = t & (IN_DIM - 1);
    const int nb0 = (t >> 6) * (DPB / 4);
    float acc[DPB / 4];
    {
        const float bb = db[o];
        #pragma unroll
        for (int n = 0; n < DPB / 4; n++) acc[n] = bb;
    }
    #pragma unroll 4
    for (int k = 0; k < OUT; k += 4) {
        const float w0 = dw[(k + 0) * IN_DIM + o];
        const float w1 = dw[(k + 1) * IN_DIM + o];
        const float w2 = dw[(k + 2) * IN_DIM + o];
        const float w3 = dw[(k + 3) * IN_DIM + o];
        #pragma unroll
        for (int n = 0; n < DPB / 4; n++) {
            float4 v = *reinterpret_cast<const float4*>(&hsm[nb0 + n][k]);
            acc[n] = fmaf(v.x, w0, acc[n]);
            acc[n] = fmaf(v.y, w1, acc[n]);
            acc[n] = fmaf(v.z, w2, acc[n]);
            acc[n] = fmaf(v.w, w3, acc[n]);
        }
    }
    #pragma unroll
    for (int n = 0; n < DPB / 4; n++)
        out[(size_t)(base + nb0 + n) * IN_DIM + o] = acc[n];
}

// ---------------------------------------------------------------------------
extern "C" void kernel_launch(void* const* d_in, const int* in_sizes, int n_in,
                              void* d_out, int out_size)
{
    const float* x   = (const float*)d_in[0];
    const int*   e32 = (const int*)d_in[1];
    const float* ew1 = (const float*)d_in[2];
    const float* eb1 = (const float*)d_in[3];
    const float* ew2 = (const float*)d_in[4];
    const float* eb2 = (const float*)d_in[5];
    const float* nw1 = (const float*)d_in[6];
    const float* nb1 = (const float*)d_in[7];
    const float* nw2 = (const float*)d_in[8];
    const float* nb2 = (const float*)d_in[9];
    const float* dw  = (const float*)d_in[10];
    const float* db  = (const float*)d_in[11];
    float*       out = (float*)d_out;

    static bool attr_done = false;
    if (!attr_done) {
        cudaFuncSetAttribute(edge_mlp_tc_kernel,
            cudaFuncAttributeMaxDynamicSharedMemorySize, EDGE_DSMEM);
        cudaFuncSetAttribute(node_mlp_tc_kernel,
            cudaFuncAttributeMaxDynamicSharedMemorySize, NODE_DSMEM);
        attr_done = true;
    }

    detect_edge_dtype_kernel<<<1, 32>>>(e32);
    convert_edges_kernel<<<(NEDGE + 255) / 256, 256>>>(e32);
    prep_weights_kernel<<<128, 256>>>(ew1, ew2, nw1, nw2);

    node_mlp_tc_kernel<<<(TOTAL_NODES + 127) / 128, 256, NODE_DSMEM>>>(x, nb1, nb2);

    edge_mlp_tc_kernel<<<(NEDGE + 63) / 64, 256, EDGE_DSMEM>>>(x, eb1, eb2);

    decode_kernel<<<TOTAL_NODES / DPB, 256>>>(dw, db, out);
}

// round 16
// speedup vs baseline: 1.0798x; 1.0036x over previous
#include <cuda_runtime.h>
#include <cuda_bf16.h>
#include <cstdint>

#define B      2
#define NNODE  50000
#define IN_DIM 64
#define HID    256
#define OUT    128
#define NEDGE  500000
#define TOTAL_NODES (B * NNODE)
#define DPB 16

// tensor kernels
#define KS1  264     // edge A1/B1 row stride (bf16): 128 hi + 128 lo + 8 pad
#define KN1  136     // node A1/B1 + all B2-chunk row stride (bf16): 128 + 8 pad
#define KS2  520     // A2 row stride (bf16): 256 hi + 256 lo + 8 pad
#define DHS2 132     // Dh row stride (f32)
#define CHB  34816   // one B2 chunk: 128*136*2 bytes

// edge smem layout (bytes)
#define EOFF_A1  0        // 128*264*2 = 67584
#define EOFF_B1  67584    // 256*264*2 = 135168 -> ends 202752
#define EOFF_A2  0        // 128*520*2 = 133120 (overlays A1+B1 after GEMM1)
#define EOFF_B2  133120   // 2 chunks  = 69632  -> ends 202752
#define EOFF_DH  133120   // 64*132*4  = 33792 (after GEMM2 done, B2 dead)
#define EDGE_DSMEM 202752

// node smem layout (bytes)
#define NOFF_A1  0        // 128*136*2 = 34816
#define NOFF_B1  34816    // 256*136*2 = 69632 -> ends 104448
#define NOFF_A2  0        // 133120
#define NOFF_B2  133120   // 69632 -> ends 202752
#define NOFF_DH  133120
#define NODE_DSMEM 202752

// ---------------------------------------------------------------------------
// device globals (allocation-guard-safe)
// ---------------------------------------------------------------------------
__device__ float g_H[(size_t)B * NNODE * OUT];
__device__ int   g_eu[NEDGE];
__device__ int   g_ev[NEDGE];
__device__ int   g_is64;
__device__ __align__(16) __nv_bfloat16 g_B1bf[256 * KS1];     // edge ew1 image
__device__ __align__(16) __nv_bfloat16 g_B2ch[4 * 128 * KN1]; // edge ew2 chunks
__device__ __align__(16) __nv_bfloat16 g_NB1bf[256 * KN1];    // node nw1 image
__device__ __align__(16) __nv_bfloat16 g_NB2ch[4 * 128 * KN1];// node nw2 chunks

// ---------------------------------------------------------------------------
// helpers
// ---------------------------------------------------------------------------
static __device__ __forceinline__ void mma16816(float* d, const uint32_t* a, const uint32_t* b)
{
    asm volatile(
        "mma.sync.aligned.m16n8k16.row.col.f32.bf16.bf16.f32 "
        "{%0,%1,%2,%3}, {%4,%5,%6,%7}, {%8,%9}, {%0,%1,%2,%3};"
        : "+f"(d[0]), "+f"(d[1]), "+f"(d[2]), "+f"(d[3])
        : "r"(a[0]), "r"(a[1]), "r"(a[2]), "r"(a[3]), "r"(b[0]), "r"(b[1]));
}

static __device__ __forceinline__ void ldsm4(uint32_t& r0, uint32_t& r1, uint32_t& r2,
                                             uint32_t& r3, uint32_t addr)
{
    asm volatile("ldmatrix.sync.aligned.m8n8.x4.shared.b16 {%0,%1,%2,%3}, [%4];"
                 : "=r"(r0), "=r"(r1), "=r"(r2), "=r"(r3) : "r"(addr));
}

static __device__ __forceinline__ void cp16(uint32_t dst, const void* src)
{
    asm volatile("cp.async.cg.shared.global [%0], [%1], 16;" :: "r"(dst), "l"(src) : "memory");
}
#define CP_COMMIT() asm volatile("cp.async.commit_group;" ::: "memory")
#define CP_WAIT0()  asm volatile("cp.async.wait_group 0;" ::: "memory")

static __device__ __forceinline__ void red_add_v4(float* p, float a, float b, float c, float d)
{
    asm volatile("red.global.add.v4.f32 [%0], {%1, %2, %3, %4};"
                 :: "l"(p), "f"(a), "f"(b), "f"(c), "f"(d) : "memory");
}

static __device__ __forceinline__ void split_store(__nv_bfloat16* hi_p, __nv_bfloat16* lo_p,
                                                   float v0, float v1)
{
    __nv_bfloat162 hp = __floats2bfloat162_rn(v0, v1);
    const float h0 = __bfloat162float(hp.x), h1 = __bfloat162float(hp.y);
    __nv_bfloat162 lp = __floats2bfloat162_rn(v0 - h0, v1 - h1);
    *(uint32_t*)hi_p = *(const uint32_t*)&hp;
    *(uint32_t*)lo_p = *(const uint32_t*)&lp;
}

// ---------------------------------------------------------------------------
// edge dtype detect + SoA normalize (proven)
// ---------------------------------------------------------------------------
__global__ void detect_edge_dtype_kernel(const int* __restrict__ e32)
{
    if (threadIdx.x == 0 && blockIdx.x == 0) {
        int all_zero = 1;
        #pragma unroll 1
        for (int i = 1; i < 256; i += 2)
            if (e32[i] != 0) { all_zero = 0; break; }
        g_is64 = all_zero;
    }
}

__global__ __launch_bounds__(256) void convert_edges_kernel(const int* __restrict__ e32)
{
    const int e = blockIdx.x * 256 + threadIdx.x;
    if (e < NEDGE) {
        if (g_is64) { g_eu[e] = e32[4 * e + 0]; g_ev[e] = e32[4 * e + 2]; }
        else        { g_eu[e] = e32[2 * e + 0]; g_ev[e] = e32[2 * e + 1]; }
    }
}

// ---------------------------------------------------------------------------
// weight prep: split fp32 -> bf16 hi/lo images
// ---------------------------------------------------------------------------
__global__ __launch_bounds__(256) void prep_weights_kernel(
    const float* __restrict__ ew1, const float* __restrict__ ew2,
    const float* __restrict__ nw1, const float* __restrict__ nw2)
{
    const int tid = blockIdx.x * 256 + threadIdx.x;
    const int stride = gridDim.x * 256;
    for (int idx = tid; idx < 256 * 128; idx += stride) {
        const int n = idx >> 7, k = idx & 127;
        const float w = ew1[k * HID + n];
        const __nv_bfloat16 hi = __float2bfloat16_rn(w);
        g_B1bf[n * KS1 + k]       = hi;
        g_B1bf[n * KS1 + 128 + k] = __float2bfloat16_rn(w - __bfloat162float(hi));
    }
    for (int idx = tid; idx < 4 * 128 * 128; idx += stride) {
        const int c = idx >> 14;
        const int r = idx & 16383;
        const int n = r >> 7, l = r & 127;
        const int k = (c & 1) * 128 + l;
        const float w = ew2[k * OUT + n];
        const __nv_bfloat16 hi = __float2bfloat16_rn(w);
        g_B2ch[(c * 128 + n) * KN1 + l] =
            (c < 2) ? hi : __float2bfloat16_rn(w - __bfloat162float(hi));
    }
    for (int idx = tid; idx < 256 * 64; idx += stride) {
        const int n = idx >> 6, k = idx & 63;
        const float w = nw1[k * HID + n];
        const __nv_bfloat16 hi = __float2bfloat16_rn(w);
        g_NB1bf[n * KN1 + k]      = hi;
        g_NB1bf[n * KN1 + 64 + k] = __float2bfloat16_rn(w - __bfloat162float(hi));
    }
    for (int idx = tid; idx < 4 * 128 * 128; idx += stride) {
        const int c = idx >> 14;
        const int r = idx & 16383;
        const int n = r >> 7, l = r & 127;
        const int k = (c & 1) * 128 + l;
        const float w = nw2[k * OUT + n];
        const __nv_bfloat16 hi = __float2bfloat16_rn(w);
        g_NB2ch[(c * 128 + n) * KN1 + l] =
            (c < 2) ? hi : __float2bfloat16_rn(w - __bfloat162float(hi));
    }
}

// ---------------------------------------------------------------------------
// shared GEMM2 (pipelined frags): warp tile 64m x 32n over full N=128;
// B2 double-buffered k-chunks; ldsm double-buffered within each pass.
// ---------------------------------------------------------------------------
static __device__ __forceinline__ void gemm2_chunked(
    float (*acc2)[4][4], const __nv_bfloat16* gB2ch,
    uint32_t sA2, uint32_t sB2, int m2, int n2t,
    int t, int lr, int lq, int lh)
{
    uint32_t aA2[4];
    #pragma unroll
    for (int mi = 0; mi < 4; mi++)
        aA2[mi] = sA2 + ((m2 + mi * 16 + lr + lq * 8) * KS2 + lh * 8) * 2;

    const int ABASE0[4] = {0, 128, 0, 128};
    const int ABASE1[2] = {256, 384};

    uint32_t af[2][4][4], bfr[2][2][4];

    #pragma unroll 1
    for (int c = 0; c < 4; c++) {
        CP_WAIT0();
        __syncthreads();
        if (c < 3) {
            const float4* src = (const float4*)(gB2ch + (size_t)(c + 1) * 128 * KN1);
            const uint32_t dst = sB2 + ((c + 1) & 1) * CHB;
            #pragma unroll 1
            for (int i = t; i < 2176; i += 256) cp16(dst + i * 16, src + i);
            CP_COMMIT();
        }
        const uint32_t sBc = sB2 + (c & 1) * CHB;
        uint32_t bA[2];
        #pragma unroll
        for (int grp = 0; grp < 2; grp++)
            bA[grp] = sBc + ((n2t + grp * 16 + lh * 8 + lr) * KN1 + lq * 8) * 2;

        const int npass = (c < 2) ? 2 : 1;
        #pragma unroll 1
        for (int p = 0; p < npass; p++) {
            const int ab = (p == 0) ? ABASE0[c] : ABASE1[c];
            // preload k16=0
            #pragma unroll
            for (int mi = 0; mi < 4; mi++)
                ldsm4(af[0][mi][0], af[0][mi][1], af[0][mi][2], af[0][mi][3],
                      aA2[mi] + ab * 2);
            #pragma unroll
            for (int j = 0; j < 2; j++)
                ldsm4(bfr[0][j][0], bfr[0][j][1], bfr[0][j][2], bfr[0][j][3], bA[j]);
            #pragma unroll 2
            for (int k16 = 0; k16 < 8; k16++) {
                const int cur = k16 & 1, nxt = cur ^ 1;
                if (k16 < 7) {
                    const int ka = (ab + (k16 + 1) * 16) * 2;
                    const int kb = (k16 + 1) * 32;
                    #pragma unroll
                    for (int mi = 0; mi < 4; mi++)
                        ldsm4(af[nxt][mi][0], af[nxt][mi][1], af[nxt][mi][2], af[nxt][mi][3],
                              aA2[mi] + ka);
                    #pragma unroll
                    for (int j = 0; j < 2; j++)
                        ldsm4(bfr[nxt][j][0], bfr[nxt][j][1], bfr[nxt][j][2], bfr[nxt][j][3],
                              bA[j] + kb);
                }
                #pragma unroll
                for (int nt = 0; nt < 4; nt++) {
                    const uint32_t* bp = (nt & 1) ? &bfr[cur][nt >> 1][2] : &bfr[cur][nt >> 1][0];
                    #pragma unroll
                    for (int mi = 0; mi < 4; mi++)
                        mma16816(acc2[mi][nt], af[cur][mi], bp);
                }
            }
        }
    }
    __syncthreads();   // all MMAs done; B2 buffers dead (Dh overlays them)
}

// ---------------------------------------------------------------------------
// Edge MLP v10 (pipelined frags)
// ---------------------------------------------------------------------------
__global__ __launch_bounds__(256, 1) void edge_mlp_tc_kernel(
    const float* __restrict__ x,
    const float* __restrict__ eb1, const float* __restrict__ eb2)
{
    extern __shared__ __align__(16) char smc[];
    __nv_bfloat16* A1 = (__nv_bfloat16*)(smc + EOFF_A1);
    __nv_bfloat16* B1 = (__nv_bfloat16*)(smc + EOFF_B1);
    __nv_bfloat16* A2 = (__nv_bfloat16*)(smc + EOFF_A2);
    float*         Dh = (float*)(smc + EOFF_DH);

    __shared__ int   us[64], vs[64];
    __shared__ float eb1f[HID], eb2f[OUT];

    const int t   = threadIdx.x;
    const int wid = t >> 5;
    const int lid = t & 31;
    const int g   = lid >> 2;
    const int tg  = lid & 3;
    const int lr  = lid & 7;
    const int lq  = (lid >> 3) & 1;
    const int lh  = lid >> 4;
    const int e0  = blockIdx.x * 64;
    const int count = min(64, NEDGE - e0);

    const uint32_t sA1 = (uint32_t)__cvta_generic_to_shared(A1);
    const uint32_t sB1 = (uint32_t)__cvta_generic_to_shared(B1);
    const uint32_t sA2 = (uint32_t)__cvta_generic_to_shared(A2);
    const uint32_t sB2 = (uint32_t)__cvta_generic_to_shared(smc + EOFF_B2);

    if (t < 64) {
        const int e = min(e0 + t, NEDGE - 1);
        us[t] = g_eu[e]; vs[t] = g_ev[e];
    }
    eb1f[t] = eb1[t];
    if (t < OUT) eb2f[t] = eb2[t];

    {   // prefetch B1 (135168 B) — overlaps gather
        const float4* src = (const float4*)g_B1bf;
        #pragma unroll 1
        for (int i = t; i < 8448; i += 256) cp16(sB1 + i * 16, src + i);
        CP_COMMIT();
    }
    __syncthreads();

    // gather: rows 0-63 batch0, 64-127 batch1
    #pragma unroll
    for (int it = 0; it < 32; it++) {
        const int q = t + it * 256;
        const int m = q >> 6;
        const int c = (q & 63) * 2;
        const int node = (c < IN_DIM) ? us[m & 63] : vs[m & 63];
        const float2 xv = *(const float2*)
            &x[((size_t)(m >> 6) * NNODE + node) * IN_DIM + (c & (IN_DIM - 1))];
        split_store(A1 + m * KS1 + c, A1 + m * KS1 + 128 + c, xv.x, xv.y);
    }
    CP_WAIT0();
    __syncthreads();

    // ---- GEMM1: warp tile 64m x 32n, 2 n-halves, pipelined frags ----
    const int m1 = (wid >> 2) * 64;
    const int n1 = (wid & 3) * 32;
    uint32_t aAddr1[4], bAddr1[4];
    #pragma unroll
    for (int mi = 0; mi < 4; mi++)
        aAddr1[mi] = sA1 + ((m1 + mi * 16 + lr + lq * 8) * KS1 + lh * 8) * 2;
    #pragma unroll
    for (int h = 0; h < 2; h++)
        #pragma unroll
        for (int grp = 0; grp < 2; grp++)
            bAddr1[h * 2 + grp] = sB1 + ((h * 128 + n1 + grp * 16 + lh * 8 + lr) * KS1 + lq * 8) * 2;

    float acc1[2][4][4][4] = {};
    {
        uint32_t af[2][4][4], bfr[2][4][4];
        // it = seg*8 + k16; ka = ((seg==1)?256:0) + k16*32 bytes; kb = ((seg==2)?256:0) + k16*32
        #define E1_KA(IT) ((((IT) >> 3) == 1 ? 256 : 0) + ((IT) & 7) * 32)
        #define E1_KB(IT) ((((IT) >> 3) == 2 ? 256 : 0) + ((IT) & 7) * 32)
        #pragma unroll
        for (int mi = 0; mi < 4; mi++)
            ldsm4(af[0][mi][0], af[0][mi][1], af[0][mi][2], af[0][mi][3], aAddr1[mi] + E1_KA(0));
        #pragma unroll
        for (int j = 0; j < 4; j++)
            ldsm4(bfr[0][j][0], bfr[0][j][1], bfr[0][j][2], bfr[0][j][3], bAddr1[j] + E1_KB(0));
        #pragma unroll 2
        for (int it = 0; it < 24; it++) {
            const int cur = it & 1, nxt = cur ^ 1;
            if (it < 23) {
                const int ka = E1_KA(it + 1);
                const int kb = E1_KB(it + 1);
                #pragma unroll
                for (int mi = 0; mi < 4; mi++)
                    ldsm4(af[nxt][mi][0], af[nxt][mi][1], af[nxt][mi][2], af[nxt][mi][3],
                          aAddr1[mi] + ka);
                #pragma unroll
                for (int j = 0; j < 4; j++)
                    ldsm4(bfr[nxt][j][0], bfr[nxt][j][1], bfr[nxt][j][2], bfr[nxt][j][3],
                          bAddr1[j] + kb);
            }
            #pragma unroll
            for (int h = 0; h < 2; h++)
                #pragma unroll
                for (int nt = 0; nt < 4; nt++) {
                    const uint32_t* bp = (nt & 1) ? &bfr[cur][h * 2 + (nt >> 1)][2]
                                                  : &bfr[cur][h * 2 + (nt >> 1)][0];
                    #pragma unroll
                    for (int mi = 0; mi < 4; mi++)
                        mma16816(acc1[h][mi][nt], af[cur][mi], bp);
                }
        }
        #undef E1_KA
        #undef E1_KB
    }
    __syncthreads();

    {   // prefetch B2 chunk0 (region = dead B1 tail)
        const float4* src = (const float4*)g_B2ch;
        #pragma unroll 1
        for (int i = t; i < 2176; i += 256) cp16(sB2 + i * 16, src + i);
        CP_COMMIT();
    }

    // epilogue G1 -> A2 (overlaps chunk0 prefetch)
    #pragma unroll
    for (int h = 0; h < 2; h++)
        #pragma unroll
        for (int mi = 0; mi < 4; mi++) {
            const int r0 = m1 + mi * 16 + g;
            #pragma unroll
            for (int nt = 0; nt < 4; nt++) {
                const int c = h * 128 + n1 + nt * 8 + tg * 2;
                const float b0 = eb1f[c], b1 = eb1f[c + 1];
                const float v0 = fmaxf(acc1[h][mi][nt][0] + b0, 0.f);
                const float v1 = fmaxf(acc1[h][mi][nt][1] + b1, 0.f);
                const float v2 = fmaxf(acc1[h][mi][nt][2] + b0, 0.f);
                const float v3 = fmaxf(acc1[h][mi][nt][3] + b1, 0.f);
                __nv_bfloat16* r0p = A2 + (size_t)r0 * KS2;
                __nv_bfloat16* r1p = A2 + (size_t)(r0 + 8) * KS2;
                split_store(r0p + c, r0p + 256 + c, v0, v1);
                split_store(r1p + c, r1p + 256 + c, v2, v3);
            }
        }

    // ---- GEMM2 chunked ----
    const int m2  = (wid >> 2) * 64;
    const int n2t = (wid & 3) * 32;
    float acc2[4][4][4] = {};
    gemm2_chunked(acc2, g_B2ch, sA2, sB2, m2, n2t, t, lr, lq, lh);

    // ---- epilogue + scatter, phased by batch ----
    #pragma unroll 1
    for (int pg = 0; pg < 2; pg++) {
        if ((m2 >> 6) == pg) {
            #pragma unroll
            for (int mi = 0; mi < 4; mi++) {
                const int r = (m2 - pg * 64) + mi * 16 + g;
                #pragma unroll
                for (int nt = 0; nt < 4; nt++) {
                    const int cc = n2t + nt * 8 + tg * 2;
                    const float b0 = eb2f[cc], b1 = eb2f[cc + 1];
                    float2 lo, hi;
                    lo.x = acc2[mi][nt][0] + b0;
                    lo.y = acc2[mi][nt][1] + b1;
                    hi.x = acc2[mi][nt][2] + b0;
                    hi.y = acc2[mi][nt][3] + b1;
                    *(float2*)&Dh[r * DHS2 + cc]       = lo;
                    *(float2*)&Dh[(r + 8) * DHS2 + cc] = hi;
                }
            }
        }
        __syncthreads();
        float* Hb = g_H + (size_t)pg * NNODE * OUT;
        #pragma unroll 1
        for (int i = t; i < 2048; i += 256) {
            const int r  = i >> 5;
            const int c4 = (i & 31) * 4;
            if (r < count) {
                const float4 vv = *(const float4*)&Dh[r * DHS2 + c4];
                red_add_v4(&Hb[(size_t)us[r] * OUT + c4], vv.x, vv.y, vv.z, vv.w);
                red_add_v4(&Hb[(size_t)vs[r] * OUT + c4], vv.x, vv.y, vv.z, vv.w);
            }
        }
        __syncthreads();
    }
}

// ---------------------------------------------------------------------------
// Node MLP v10 (tensor, pipelined frags)
// ---------------------------------------------------------------------------
__global__ __launch_bounds__(256, 1) void node_mlp_tc_kernel(
    const float* __restrict__ x,
    const float* __restrict__ nb1, const float* __restrict__ nb2)
{
    extern __shared__ __align__(16) char smc[];
    __nv_bfloat16* A1 = (__nv_bfloat16*)(smc + NOFF_A1);
    __nv_bfloat16* B1 = (__nv_bfloat16*)(smc + NOFF_B1);
    __nv_bfloat16* A2 = (__nv_bfloat16*)(smc + NOFF_A2);
    float*         Dh = (float*)(smc + NOFF_DH);

    __shared__ float nb1f[HID], nb2f[OUT];

    const int t   = threadIdx.x;
    const int wid = t >> 5;
    const int lid = t & 31;
    const int g   = lid >> 2;
    const int tg  = lid & 3;
    const int lr  = lid & 7;
    const int lq  = (lid >> 3) & 1;
    const int lh  = lid >> 4;
    const int base = blockIdx.x * 128;

    const uint32_t sA1 = (uint32_t)__cvta_generic_to_shared(A1);
    const uint32_t sB1 = (uint32_t)__cvta_generic_to_shared(B1);
    const uint32_t sA2 = (uint32_t)__cvta_generic_to_shared(A2);
    const uint32_t sB2 = (uint32_t)__cvta_generic_to_shared(smc + NOFF_B2);

    nb1f[t] = nb1[t];
    if (t < OUT) nb2f[t] = nb2[t];

    {   // prefetch B1 (69632 B) — overlaps A load
        const float4* src = (const float4*)g_NB1bf;
        #pragma unroll 1
        for (int i = t; i < 4352; i += 256) cp16(sB1 + i * 16, src + i);
        CP_COMMIT();
    }

    // load x rows (clamped), split hi|lo into A1 [128m][64hi|64lo]
    #pragma unroll
    for (int it = 0; it < 16; it++) {
        const int q = t + it * 256;
        const int m = q >> 5;
        const int c = (q & 31) * 2;
        const int row = min(base + m, TOTAL_NODES - 1);
        const float2 xv = *(const float2*)&x[(size_t)row * IN_DIM + c];
        split_store(A1 + m * KN1 + c, A1 + m * KN1 + 64 + c, xv.x, xv.y);
    }
    CP_WAIT0();
    __syncthreads();

    // ---- GEMM1: K=64, 3 segs x 4 k16, pipelined frags ----
    const int m1 = (wid >> 2) * 64;
    const int n1 = (wid & 3) * 32;
    uint32_t aAddr1[4], bAddr1[4];
    #pragma unroll
    for (int mi = 0; mi < 4; mi++)
        aAddr1[mi] = sA1 + ((m1 + mi * 16 + lr + lq * 8) * KN1 + lh * 8) * 2;
    #pragma unroll
    for (int h = 0; h < 2; h++)
        #pragma unroll
        for (int grp = 0; grp < 2; grp++)
            bAddr1[h * 2 + grp] = sB1 + ((h * 128 + n1 + grp * 16 + lh * 8 + lr) * KN1 + lq * 8) * 2;

    float acc1[2][4][4][4] = {};
    {
        uint32_t af[2][4][4], bfr[2][4][4];
        #define N1_KA(IT) ((((IT) >> 2) == 1 ? 128 : 0) + ((IT) & 3) * 32)
        #define N1_KB(IT) ((((IT) >> 2) == 2 ? 128 : 0) + ((IT) & 3) * 32)
        #pragma unroll
        for (int mi = 0; mi < 4; mi++)
            ldsm4(af[0][mi][0], af[0][mi][1], af[0][mi][2], af[0][mi][3], aAddr1[mi] + N1_KA(0));
        #pragma unroll
        for (int j = 0; j < 4; j++)
            ldsm4(bfr[0][j][0], bfr[0][j][1], bfr[0][j][2], bfr[0][j][3], bAddr1[j] + N1_KB(0));
        #pragma unroll 2
        for (int it = 0; it < 12; it++) {
            const int cur = it & 1, nxt = cur ^ 1;
            if (it < 11) {
                const int ka = N1_KA(it + 1);
                const int kb = N1_KB(it + 1);
                #pragma unroll
                for (int mi = 0; mi < 4; mi++)
                    ldsm4(af[nxt][mi][0], af[nxt][mi][1], af[nxt][mi][2], af[nxt][mi][3],
                          aAddr1[mi] + ka);
                #pragma unroll
                for (int j = 0; j < 4; j++)
                    ldsm4(bfr[nxt][j][0], bfr[nxt][j][1], bfr[nxt][j][2], bfr[nxt][j][3],
                          bAddr1[j] + kb);
            }
            #pragma unroll
            for (int h = 0; h < 2; h++)
                #pragma unroll
                for (int nt = 0; nt < 4; nt++) {
                    const uint32_t* bp = (nt & 1) ? &bfr[cur][h * 2 + (nt >> 1)][2]
                                                  : &bfr[cur][h * 2 + (nt >> 1)][0];
                    #pragma unroll
                    for (int mi = 0; mi < 4; mi++)
                        mma16816(acc1[h][mi][nt], af[cur][mi], bp);
                }
        }
        #undef N1_KA
        #undef N1_KB
    }
    __syncthreads();

    {   // prefetch B2 chunk0
        const float4* src = (const float4*)g_NB2ch;
        #pragma unroll 1
        for (int i = t; i < 2176; i += 256) cp16(sB2 + i * 16, src + i);
        CP_COMMIT();
    }

    // epilogue G1 -> A2
    #pragma unroll
    for (int h = 0; h < 2; h++)
        #pragma unroll
        for (int mi = 0; mi < 4; mi++) {
            const int r0 = m1 + mi * 16 + g;
            #pragma unroll
            for (int nt = 0; nt < 4; nt++) {
                const int c = h * 128 + n1 + nt * 8 + tg * 2;
                const float b0 = nb1f[c], b1 = nb1f[c + 1];
                const float v0 = fmaxf(acc1[h][mi][nt][0] + b0, 0.f);
                const float v1 = fmaxf(acc1[h][mi][nt][1] + b1, 0.f);
                const float v2 = fmaxf(acc1[h][mi][nt][2] + b0, 0.f);
                const float v3 = fmaxf(acc1[h][mi][nt][3] + b1, 0.f);
                __nv_bfloat16* r0p = A2 + (size_t)r0 * KS2;
                __nv_bfloat16* r1p = A2 + (size_t)(r0 + 8) * KS2;
                split_store(r0p + c, r0p + 256 + c, v0, v1);
                split_store(r1p + c, r1p + 256 + c, v2, v3);
            }
        }

    // ---- GEMM2 chunked ----
    const int m2  = (wid >> 2) * 64;
    const int n2t = (wid & 3) * 32;
    float acc2[4][4][4] = {};
    gemm2_chunked(acc2, g_NB2ch, sA2, sB2, m2, n2t, t, lr, lq, lh);

    // ---- epilogue + store, phased in 64-row groups ----
    #pragma unroll 1
    for (int pg = 0; pg < 2; pg++) {
        if ((m2 >> 6) == pg) {
            #pragma unroll
            for (int mi = 0; mi < 4; mi++) {
                const int r = (m2 - pg * 64) + mi * 16 + g;
                #pragma unroll
                for (int nt = 0; nt < 4; nt++) {
                    const int cc = n2t + nt * 8 + tg * 2;
                    const float b0 = nb2f[cc], b1 = nb2f[cc + 1];
                    float2 lo, hi;
                    lo.x = acc2[mi][nt][0] + b0;
                    lo.y = acc2[mi][nt][1] + b1;
                    hi.x = acc2[mi][nt][2] + b0;
                    hi.y = acc2[mi][nt][3] + b1;
                    *(float2*)&Dh[r * DHS2 + cc]       = lo;
                    *(float2*)&Dh[(r + 8) * DHS2 + cc] = hi;
                }
            }
        }
        __syncthreads();
        #pragma unroll 1
        for (int i = t; i < 2048; i += 256) {
            const int r   = i >> 5;
            const int c4  = (i & 31) * 4;
            const int row = base + pg * 64 + r;
            if (row < TOTAL_NODES)
                *(float4*)&g_H[(size_t)row * OUT + c4] = *(const float4*)&Dh[r * DHS2 + c4];
        }
        __syncthreads();
    }
}

// ---------------------------------------------------------------------------
// decode: out = H @ dw + db (unchanged)
// ---------------------------------------------------------------------------
__global__ __launch_bounds__(256) void decode_kernel(
    const float* __restrict__ dw, const float* __restrict__ db,
    float* __restrict__ out)
{
    __shared__ __align__(16) float hsm[DPB][OUT];

    const int base = blockIdx.x * DPB;
    const int t = threadIdx.x;

    for (int i = t; i < DPB * OUT; i += 256)
        hsm[i / OUT][i % OUT] = g_H[(size_t)base * OUT + i];
    __syncthreads();

    const int o   = t & (IN_DIM - 1);
    const int nb0 = (t >> 6) * (DPB / 4);
    float acc[DPB / 4];
    {
        const float bb = db[o];
        #pragma unroll
        for (int n = 0; n < DPB / 4; n++) acc[n] = bb;
    }
    #pragma unroll 4
    for (int k = 0; k < OUT; k += 4) {
        const float w0 = dw[(k + 0) * IN_DIM + o];
        const float w1 = dw[(k + 1) * IN_DIM + o];
        const float w2 = dw[(k + 2) * IN_DIM + o];
        const float w3 = dw[(k + 3) * IN_DIM + o];
        #pragma unroll
        for (int n = 0; n < DPB / 4; n++) {
            float4 v = *reinterpret_cast<const float4*>(&hsm[nb0 + n][k]);
            acc[n] = fmaf(v.x, w0, acc[n]);
            acc[n] = fmaf(v.y, w1, acc[n]);
            acc[n] = fmaf(v.z, w2, acc[n]);
            acc[n] = fmaf(v.w, w3, acc[n]);
        }
    }
    #pragma unroll
    for (int n = 0; n < DPB / 4; n++)
        out[(size_t)(base + nb0 + n) * IN_DIM + o] = acc[n];
}

// ---------------------------------------------------------------------------
extern "C" void kernel_launch(void* const* d_in, const int* in_sizes, int n_in,
                              void* d_out, int out_size)
{
    const float* x   = (const float*)d_in[0];
    const int*   e32 = (const int*)d_in[1];
    const float* ew1 = (const float*)d_in[2];
    const float* eb1 = (const float*)d_in[3];
    const float* ew2 = (const float*)d_in[4];
    const float* eb2 = (const float*)d_in[5];
    const float* nw1 = (const float*)d_in[6];
    const float* nb1 = (const float*)d_in[7];
    const float* nw2 = (const float*)d_in[8];
    const float* nb2 = (const float*)d_in[9];
    const float* dw  = (const float*)d_in[10];
    const float* db  = (const float*)d_in[11];
    float*       out = (float*)d_out;

    static bool attr_done = false;
    if (!attr_done) {
        cudaFuncSetAttribute(edge_mlp_tc_kernel,
            cudaFuncAttributeMaxDynamicSharedMemorySize, EDGE_DSMEM);
        cudaFuncSetAttribute(node_mlp_tc_kernel,
            cudaFuncAttributeMaxDynamicSharedMemorySize, NODE_DSMEM);
        attr_done = true;
    }

    detect_edge_dtype_kernel<<<1, 32>>>(e32);
    convert_edges_kernel<<<(NEDGE + 255) / 256, 256>>>(e32);
    prep_weights_kernel<<<128, 256>>>(ew1, ew2, nw1, nw2);

    node_mlp_tc_kernel<<<(TOTAL_NODES + 127) / 128, 256, NODE_DSMEM>>>(x, nb1, nb2);

    edge_mlp_tc_kernel<<<(NEDGE + 63) / 64, 256, EDGE_DSMEM>>>(x, eb1, eb2);

    decode_kernel<<<TOTAL_NODES / DPB, 256>>>(dw, db, out);
}

// round 17
// speedup vs baseline: 1.1820x; 1.0947x over previous
#include <cuda_runtime.h>
#include <cuda_bf16.h>
#include <cstdint>

#define B      2
#define NNODE  50000
#define IN_DIM 64
#define HID    256
#define OUT    128
#define NEDGE  500000
#define TOTAL_NODES (B * NNODE)
#define DPB 16
#define NT  512   // threads per TC block

// tensor kernels
#define KS1  264     // edge A1/B1 row stride (bf16)
#define KN1  136     // node A1/B1 + B2-chunk row stride (bf16)
#define KS2  520     // A2 row stride (bf16)
#define DHS2 132     // Dh row stride (f32)
#define CHB  34816   // one B2 chunk: 128*136*2 bytes

// edge smem layout (bytes)
#define EOFF_A1  0
#define EOFF_B1  67584
#define EOFF_A2  0
#define EOFF_B2  133120
#define EOFF_DH  133120
#define EDGE_DSMEM 202752

// node smem layout (bytes)
#define NOFF_A1  0
#define NOFF_B1  34816
#define NOFF_A2  0
#define NOFF_B2  133120
#define NOFF_DH  133120
#define NODE_DSMEM 202752

// ---------------------------------------------------------------------------
__device__ float g_H[(size_t)B * NNODE * OUT];
__device__ int   g_eu[NEDGE];
__device__ int   g_ev[NEDGE];
__device__ int   g_is64;
__device__ __align__(16) __nv_bfloat16 g_B1bf[256 * KS1];
__device__ __align__(16) __nv_bfloat16 g_B2ch[4 * 128 * KN1];
__device__ __align__(16) __nv_bfloat16 g_NB1bf[256 * KN1];
__device__ __align__(16) __nv_bfloat16 g_NB2ch[4 * 128 * KN1];

// ---------------------------------------------------------------------------
static __device__ __forceinline__ void mma16816(float* d, const uint32_t* a, const uint32_t* b)
{
    asm volatile(
        "mma.sync.aligned.m16n8k16.row.col.f32.bf16.bf16.f32 "
        "{%0,%1,%2,%3}, {%4,%5,%6,%7}, {%8,%9}, {%0,%1,%2,%3};"
        : "+f"(d[0]), "+f"(d[1]), "+f"(d[2]), "+f"(d[3])
        : "r"(a[0]), "r"(a[1]), "r"(a[2]), "r"(a[3]), "r"(b[0]), "r"(b[1]));
}

static __device__ __forceinline__ void ldsm4(uint32_t& r0, uint32_t& r1, uint32_t& r2,
                                             uint32_t& r3, uint32_t addr)
{
    asm volatile("ldmatrix.sync.aligned.m8n8.x4.shared.b16 {%0,%1,%2,%3}, [%4];"
                 : "=r"(r0), "=r"(r1), "=r"(r2), "=r"(r3) : "r"(addr));
}

static __device__ __forceinline__ void cp16(uint32_t dst, const void* src)
{
    asm volatile("cp.async.cg.shared.global [%0], [%1], 16;" :: "r"(dst), "l"(src) : "memory");
}
#define CP_COMMIT() asm volatile("cp.async.commit_group;" ::: "memory")
#define CP_WAIT0()  asm volatile("cp.async.wait_group 0;" ::: "memory")

static __device__ __forceinline__ void red_add_v4(float* p, float a, float b, float c, float d)
{
    asm volatile("red.global.add.v4.f32 [%0], {%1, %2, %3, %4};"
                 :: "l"(p), "f"(a), "f"(b), "f"(c), "f"(d) : "memory");
}

static __device__ __forceinline__ void split_store(__nv_bfloat16* hi_p, __nv_bfloat16* lo_p,
                                                   float v0, float v1)
{
    __nv_bfloat162 hp = __floats2bfloat162_rn(v0, v1);
    const float h0 = __bfloat162float(hp.x), h1 = __bfloat162float(hp.y);
    __nv_bfloat162 lp = __floats2bfloat162_rn(v0 - h0, v1 - h1);
    *(uint32_t*)hi_p = *(const uint32_t*)&hp;
    *(uint32_t*)lo_p = *(const uint32_t*)&lp;
}

// ---------------------------------------------------------------------------
__global__ void detect_edge_dtype_kernel(const int* __restrict__ e32)
{
    if (threadIdx.x == 0 && blockIdx.x == 0) {
        int all_zero = 1;
        #pragma unroll 1
        for (int i = 1; i < 256; i += 2)
            if (e32[i] != 0) { all_zero = 0; break; }
        g_is64 = all_zero;
    }
}

__global__ __launch_bounds__(256) void convert_edges_kernel(const int* __restrict__ e32)
{
    const int e = blockIdx.x * 256 + threadIdx.x;
    if (e < NEDGE) {
        if (g_is64) { g_eu[e] = e32[4 * e + 0]; g_ev[e] = e32[4 * e + 2]; }
        else        { g_eu[e] = e32[2 * e + 0]; g_ev[e] = e32[2 * e + 1]; }
    }
}

// ---------------------------------------------------------------------------
__global__ __launch_bounds__(256) void prep_weights_kernel(
    const float* __restrict__ ew1, const float* __restrict__ ew2,
    const float* __restrict__ nw1, const float* __restrict__ nw2)
{
    const int tid = blockIdx.x * 256 + threadIdx.x;
    const int stride = gridDim.x * 256;
    for (int idx = tid; idx < 256 * 128; idx += stride) {
        const int n = idx >> 7, k = idx & 127;
        const float w = ew1[k * HID + n];
        const __nv_bfloat16 hi = __float2bfloat16_rn(w);
        g_B1bf[n * KS1 + k]       = hi;
        g_B1bf[n * KS1 + 128 + k] = __float2bfloat16_rn(w - __bfloat162float(hi));
    }
    for (int idx = tid; idx < 4 * 128 * 128; idx += stride) {
        const int c = idx >> 14;
        const int r = idx & 16383;
        const int n = r >> 7, l = r & 127;
        const int k = (c & 1) * 128 + l;
        const float w = ew2[k * OUT + n];
        const __nv_bfloat16 hi = __float2bfloat16_rn(w);
        g_B2ch[(c * 128 + n) * KN1 + l] =
            (c < 2) ? hi : __float2bfloat16_rn(w - __bfloat162float(hi));
    }
    for (int idx = tid; idx < 256 * 64; idx += stride) {
        const int n = idx >> 6, k = idx & 63;
        const float w = nw1[k * HID + n];
        const __nv_bfloat16 hi = __float2bfloat16_rn(w);
        g_NB1bf[n * KN1 + k]      = hi;
        g_NB1bf[n * KN1 + 64 + k] = __float2bfloat16_rn(w - __bfloat162float(hi));
    }
    for (int idx = tid; idx < 4 * 128 * 128; idx += stride) {
        const int c = idx >> 14;
        const int r = idx & 16383;
        const int n = r >> 7, l = r & 127;
        const int k = (c & 1) * 128 + l;
        const float w = nw2[k * OUT + n];
        const __nv_bfloat16 hi = __float2bfloat16_rn(w);
        g_NB2ch[(c * 128 + n) * KN1 + l] =
            (c < 2) ? hi : __float2bfloat16_rn(w - __bfloat162float(hi));
    }
}

// ---------------------------------------------------------------------------
// shared GEMM2 for 16 warps: warp tile 32m x 32n over full N=128;
// B2 double-buffered k-chunks. acc2[2][4][4].
// ---------------------------------------------------------------------------
static __device__ __forceinline__ void gemm2_chunked(
    float (*acc2)[4][4], const __nv_bfloat16* gB2ch,
    uint32_t sA2, uint32_t sB2, int m2, int n2t,
    int t, int lr, int lq, int lh)
{
    uint32_t aA2[2];
    #pragma unroll
    for (int mi = 0; mi < 2; mi++)
        aA2[mi] = sA2 + ((m2 + mi * 16 + lr + lq * 8) * KS2 + lh * 8) * 2;

    const int ABASE0[4] = {0, 128, 0, 128};
    const int ABASE1[2] = {256, 384};

    #pragma unroll 1
    for (int c = 0; c < 4; c++) {
        CP_WAIT0();
        __syncthreads();
        if (c < 3) {
            const float4* src = (const float4*)(gB2ch + (size_t)(c + 1) * 128 * KN1);
            const uint32_t dst = sB2 + ((c + 1) & 1) * CHB;
            #pragma unroll 1
            for (int i = t; i < 2176; i += NT) cp16(dst + i * 16, src + i);
            CP_COMMIT();
        }
        const uint32_t sBc = sB2 + (c & 1) * CHB;
        uint32_t bA[2];
        #pragma unroll
        for (int grp = 0; grp < 2; grp++)
            bA[grp] = sBc + ((n2t + grp * 16 + lh * 8 + lr) * KN1 + lq * 8) * 2;

        const int npass = (c < 2) ? 2 : 1;
        #pragma unroll 1
        for (int p = 0; p < npass; p++) {
            const int ab = (p == 0) ? ABASE0[c] : ABASE1[c];
            #pragma unroll 2
            for (int k16 = 0; k16 < 8; k16++) {
                const int ka = (ab + k16 * 16) * 2;
                const int kb = k16 * 32;
                uint32_t a[2][4], bb[2][4];
                #pragma unroll
                for (int mi = 0; mi < 2; mi++)
                    ldsm4(a[mi][0], a[mi][1], a[mi][2], a[mi][3], aA2[mi] + ka);
                #pragma unroll
                for (int j = 0; j < 2; j++)
                    ldsm4(bb[j][0], bb[j][1], bb[j][2], bb[j][3], bA[j] + kb);
                #pragma unroll
                for (int nt = 0; nt < 4; nt++) {
                    const uint32_t* bp = (nt & 1) ? &bb[nt >> 1][2] : &bb[nt >> 1][0];
                    #pragma unroll
                    for (int mi = 0; mi < 2; mi++)
                        mma16816(acc2[mi][nt], a[mi], bp);
                }
            }
        }
    }
    __syncthreads();
}

// ---------------------------------------------------------------------------
// Edge MLP v11: 512 threads, 16 warps
// ---------------------------------------------------------------------------
__global__ __launch_bounds__(NT, 1) void edge_mlp_tc_kernel(
    const float* __restrict__ x,
    const float* __restrict__ eb1, const float* __restrict__ eb2)
{
    extern __shared__ __align__(16) char smc[];
    __nv_bfloat16* A1 = (__nv_bfloat16*)(smc + EOFF_A1);
    __nv_bfloat16* A2 = (__nv_bfloat16*)(smc + EOFF_A2);
    float*         Dh = (float*)(smc + EOFF_DH);

    __shared__ int   us[64], vs[64];
    __shared__ float eb1f[HID], eb2f[OUT];

    const int t   = threadIdx.x;
    const int wid = t >> 5;
    const int lid = t & 31;
    const int g   = lid >> 2;
    const int tg  = lid & 3;
    const int lr  = lid & 7;
    const int lq  = (lid >> 3) & 1;
    const int lh  = lid >> 4;
    const int e0  = blockIdx.x * 64;
    const int count = min(64, NEDGE - e0);

    const uint32_t sA1 = (uint32_t)__cvta_generic_to_shared(A1);
    const uint32_t sB1 = (uint32_t)__cvta_generic_to_shared(smc + EOFF_B1);
    const uint32_t sA2 = (uint32_t)__cvta_generic_to_shared(A2);
    const uint32_t sB2 = (uint32_t)__cvta_generic_to_shared(smc + EOFF_B2);

    if (t < 64) {
        const int e = min(e0 + t, NEDGE - 1);
        us[t] = g_eu[e]; vs[t] = g_ev[e];
    }
    if (t < HID) eb1f[t] = eb1[t];
    if (t < OUT) eb2f[t] = eb2[t];

    {   // prefetch B1 (135168 B) — overlaps gather
        const float4* src = (const float4*)g_B1bf;
        #pragma unroll 1
        for (int i = t; i < 8448; i += NT) cp16(sB1 + i * 16, src + i);
        CP_COMMIT();
    }
    __syncthreads();

    // gather: 8192 float2; rows 0-63 batch0, 64-127 batch1
    #pragma unroll
    for (int it = 0; it < 16; it++) {
        const int q = t + it * NT;
        const int m = q >> 6;
        const int c = (q & 63) * 2;
        const int node = (c < IN_DIM) ? us[m & 63] : vs[m & 63];
        const float2 xv = *(const float2*)
            &x[((size_t)(m >> 6) * NNODE + node) * IN_DIM + (c & (IN_DIM - 1))];
        split_store(A1 + m * KS1 + c, A1 + m * KS1 + 128 + c, xv.x, xv.y);
    }
    CP_WAIT0();
    __syncthreads();

    // ---- GEMM1: 16 warps, warp tile 32m x 32n x 2 n-halves ----
    const int m1 = (wid >> 2) * 32;
    const int n1 = (wid & 3) * 32;
    uint32_t aAddr1[2], bAddr1[4];
    #pragma unroll
    for (int mi = 0; mi < 2; mi++)
        aAddr1[mi] = sA1 + ((m1 + mi * 16 + lr + lq * 8) * KS1 + lh * 8) * 2;
    #pragma unroll
    for (int h = 0; h < 2; h++)
        #pragma unroll
        for (int grp = 0; grp < 2; grp++)
            bAddr1[h * 2 + grp] = sB1 + ((h * 128 + n1 + grp * 16 + lh * 8 + lr) * KS1 + lq * 8) * 2;

    float acc1[2][2][4][4] = {};
    #pragma unroll 1
    for (int seg = 0; seg < 3; seg++) {
        const int aofs = ((seg == 1) ? 128 : 0) * 2;
        const int bofs = ((seg == 2) ? 128 : 0) * 2;
        #pragma unroll 2
        for (int k16 = 0; k16 < 8; k16++) {
            const int ka = aofs + k16 * 32;
            const int kb = bofs + k16 * 32;
            uint32_t a[2][4], bb[4][4];
            #pragma unroll
            for (int mi = 0; mi < 2; mi++)
                ldsm4(a[mi][0], a[mi][1], a[mi][2], a[mi][3], aAddr1[mi] + ka);
            #pragma unroll
            for (int j = 0; j < 4; j++)
                ldsm4(bb[j][0], bb[j][1], bb[j][2], bb[j][3], bAddr1[j] + kb);
            #pragma unroll
            for (int h = 0; h < 2; h++)
                #pragma unroll
                for (int nt = 0; nt < 4; nt++) {
                    const uint32_t* bp = (nt & 1) ? &bb[h * 2 + (nt >> 1)][2]
                                                  : &bb[h * 2 + (nt >> 1)][0];
                    #pragma unroll
                    for (int mi = 0; mi < 2; mi++)
                        mma16816(acc1[h][mi][nt], a[mi], bp);
                }
        }
    }
    __syncthreads();

    {   // prefetch B2 chunk0
        const float4* src = (const float4*)g_B2ch;
        #pragma unroll 1
        for (int i = t; i < 2176; i += NT) cp16(sB2 + i * 16, src + i);
        CP_COMMIT();
    }

    // epilogue G1 -> A2
    #pragma unroll
    for (int h = 0; h < 2; h++)
        #pragma unroll
        for (int mi = 0; mi < 2; mi++) {
            const int r0 = m1 + mi * 16 + g;
            #pragma unroll
            for (int nt = 0; nt < 4; nt++) {
                const int c = h * 128 + n1 + nt * 8 + tg * 2;
                const float b0 = eb1f[c], b1 = eb1f[c + 1];
                const float v0 = fmaxf(acc1[h][mi][nt][0] + b0, 0.f);
                const float v1 = fmaxf(acc1[h][mi][nt][1] + b1, 0.f);
                const float v2 = fmaxf(acc1[h][mi][nt][2] + b0, 0.f);
                const float v3 = fmaxf(acc1[h][mi][nt][3] + b1, 0.f);
                __nv_bfloat16* r0p = A2 + (size_t)r0 * KS2;
                __nv_bfloat16* r1p = A2 + (size_t)(r0 + 8) * KS2;
                split_store(r0p + c, r0p + 256 + c, v0, v1);
                split_store(r1p + c, r1p + 256 + c, v2, v3);
            }
        }

    // ---- GEMM2 chunked (16 warps: 32m x 32n) ----
    const int m2  = (wid >> 2) * 32;
    const int n2t = (wid & 3) * 32;
    float acc2[2][4][4] = {};
    gemm2_chunked(acc2, g_B2ch, sA2, sB2, m2, n2t, t, lr, lq, lh);

    // ---- epilogue + scatter, phased by batch ----
    #pragma unroll 1
    for (int pg = 0; pg < 2; pg++) {
        if ((m2 >> 6) == pg) {
            #pragma unroll
            for (int mi = 0; mi < 2; mi++) {
                const int r = (m2 - pg * 64) + mi * 16 + g;
                #pragma unroll
                for (int nt = 0; nt < 4; nt++) {
                    const int cc = n2t + nt * 8 + tg * 2;
                    const float b0 = eb2f[cc], b1 = eb2f[cc + 1];
                    float2 lo, hi;
                    lo.x = acc2[mi][nt][0] + b0;
                    lo.y = acc2[mi][nt][1] + b1;
                    hi.x = acc2[mi][nt][2] + b0;
                    hi.y = acc2[mi][nt][3] + b1;
                    *(float2*)&Dh[r * DHS2 + cc]       = lo;
                    *(float2*)&Dh[(r + 8) * DHS2 + cc] = hi;
                }
            }
        }
        __syncthreads();
        float* Hb = g_H + (size_t)pg * NNODE * OUT;
        #pragma unroll 1
        for (int i = t; i < 2048; i += NT) {
            const int r  = i >> 5;
            const int c4 = (i & 31) * 4;
            if (r < count) {
                const float4 vv = *(const float4*)&Dh[r * DHS2 + c4];
                red_add_v4(&Hb[(size_t)us[r] * OUT + c4], vv.x, vv.y, vv.z, vv.w);
                red_add_v4(&Hb[(size_t)vs[r] * OUT + c4], vv.x, vv.y, vv.z, vv.w);
            }
        }
        __syncthreads();
    }
}

// ---------------------------------------------------------------------------
// Node MLP v11: 512 threads, 16 warps
// ---------------------------------------------------------------------------
__global__ __launch_bounds__(NT, 1) void node_mlp_tc_kernel(
    const float* __restrict__ x,
    const float* __restrict__ nb1, const float* __restrict__ nb2)
{
    extern __shared__ __align__(16) char smc[];
    __nv_bfloat16* A1 = (__nv_bfloat16*)(smc + NOFF_A1);
    __nv_bfloat16* A2 = (__nv_bfloat16*)(smc + NOFF_A2);
    float*         Dh = (float*)(smc + NOFF_DH);

    __shared__ float nb1f[HID], nb2f[OUT];

    const int t   = threadIdx.x;
    const int wid = t >> 5;
    const int lid = t & 31;
    const int g   = lid >> 2;
    const int tg  = lid & 3;
    const int lr  = lid & 7;
    const int lq  = (lid >> 3) & 1;
    const int lh  = lid >> 4;
    const int base = blockIdx.x * 128;

    const uint32_t sA1 = (uint32_t)__cvta_generic_to_shared(A1);
    const uint32_t sB1 = (uint32_t)__cvta_generic_to_shared(smc + NOFF_B1);
    const uint32_t sA2 = (uint32_t)__cvta_generic_to_shared(A2);
    const uint32_t sB2 = (uint32_t)__cvta_generic_to_shared(smc + NOFF_B2);

    if (t < HID) nb1f[t] = nb1[t];
    if (t < OUT) nb2f[t] = nb2[t];

    {   // prefetch B1 (69632 B)
        const float4* src = (const float4*)g_NB1bf;
        #pragma unroll 1
        for (int i = t; i < 4352; i += NT) cp16(sB1 + i * 16, src + i);
        CP_COMMIT();
    }

    // load x rows (clamped): 4096 float2
    #pragma unroll
    for (int it = 0; it < 8; it++) {
        const int q = t + it * NT;
        const int m = q >> 5;
        const int c = (q & 31) * 2;
        const int row = min(base + m, TOTAL_NODES - 1);
        const float2 xv = *(const float2*)&x[(size_t)row * IN_DIM + c];
        split_store(A1 + m * KN1 + c, A1 + m * KN1 + 64 + c, xv.x, xv.y);
    }
    CP_WAIT0();
    __syncthreads();

    // ---- GEMM1: K=64, 3 segs x 4 k16, 16 warps 32m x 32n x 2h ----
    const int m1 = (wid >> 2) * 32;
    const int n1 = (wid & 3) * 32;
    uint32_t aAddr1[2], bAddr1[4];
    #pragma unroll
    for (int mi = 0; mi < 2; mi++)
        aAddr1[mi] = sA1 + ((m1 + mi * 16 + lr + lq * 8) * KN1 + lh * 8) * 2;
    #pragma unroll
    for (int h = 0; h < 2; h++)
        #pragma unroll
        for (int grp = 0; grp < 2; grp++)
            bAddr1[h * 2 + grp] = sB1 + ((h * 128 + n1 + grp * 16 + lh * 8 + lr) * KN1 + lq * 8) * 2;

    float acc1[2][2][4][4] = {};
    #pragma unroll 1
    for (int seg = 0; seg < 3; seg++) {
        const int aofs = ((seg == 1) ? 64 : 0) * 2;
        const int bofs = ((seg == 2) ? 64 : 0) * 2;
        #pragma unroll
        for (int k16 = 0; k16 < 4; k16++) {
            const int ka = aofs + k16 * 32;
            const int kb = bofs + k16 * 32;
            uint32_t a[2][4], bb[4][4];
            #pragma unroll
            for (int mi = 0; mi < 2; mi++)
                ldsm4(a[mi][0], a[mi][1], a[mi][2], a[mi][3], aAddr1[mi] + ka);
            #pragma unroll
            for (int j = 0; j < 4; j++)
                ldsm4(bb[j][0], bb[j][1], bb[j][2], bb[j][3], bAddr1[j] + kb);
            #pragma unroll
            for (int h = 0; h < 2; h++)
                #pragma unroll
                for (int nt = 0; nt < 4; nt++) {
                    const uint32_t* bp = (nt & 1) ? &bb[h * 2 + (nt >> 1)][2]
                                                  : &bb[h * 2 + (nt >> 1)][0];
                    #pragma unroll
                    for (int mi = 0; mi < 2; mi++)
                        mma16816(acc1[h][mi][nt], a[mi], bp);
                }
        }
    }
    __syncthreads();

    {   // prefetch B2 chunk0
        const float4* src = (const float4*)g_NB2ch;
        #pragma unroll 1
        for (int i = t; i < 2176; i += NT) cp16(sB2 + i * 16, src + i);
        CP_COMMIT();
    }

    // epilogue G1 -> A2
    #pragma unroll
    for (int h = 0; h < 2; h++)
        #pragma unroll
        for (int mi = 0; mi < 2; mi++) {
            const int r0 = m1 + mi * 16 + g;
            #pragma unroll
            for (int nt = 0; nt < 4; nt++) {
                const int c = h * 128 + n1 + nt * 8 + tg * 2;
                const float b0 = nb1f[c], b1 = nb1f[c + 1];
                const float v0 = fmaxf(acc1[h][mi][nt][0] + b0, 0.f);
                const float v1 = fmaxf(acc1[h][mi][nt][1] + b1, 0.f);
                const float v2 = fmaxf(acc1[h][mi][nt][2] + b0, 0.f);
                const float v3 = fmaxf(acc1[h][mi][nt][3] + b1, 0.f);
                __nv_bfloat16* r0p = A2 + (size_t)r0 * KS2;
                __nv_bfloat16* r1p = A2 + (size_t)(r0 + 8) * KS2;
                split_store(r0p + c, r0p + 256 + c, v0, v1);
                split_store(r1p + c, r1p + 256 + c, v2, v3);
            }
        }

    // ---- GEMM2 chunked ----
    const int m2  = (wid >> 2) * 32;
    const int n2t = (wid & 3) * 32;
    float acc2[2][4][4] = {};
    gemm2_chunked(acc2, g_NB2ch, sA2, sB2, m2, n2t, t, lr, lq, lh);

    // ---- epilogue + store, phased in 64-row groups ----
    #pragma unroll 1
    for (int pg = 0; pg < 2; pg++) {
        if ((m2 >> 6) == pg) {
            #pragma unroll
            for (int mi = 0; mi < 2; mi++) {
                const int r = (m2 - pg * 64) + mi * 16 + g;
                #pragma unroll
                for (int nt = 0; nt < 4; nt++) {
                    const int cc = n2t + nt * 8 + tg * 2;
                    const float b0 = nb2f[cc], b1 = nb2f[cc + 1];
                    float2 lo, hi;
                    lo.x = acc2[mi][nt][0] + b0;
                    lo.y = acc2[mi][nt][1] + b1;
                    hi.x = acc2[mi][nt][2] + b0;
                    hi.y = acc2[mi][nt][3] + b1;
                    *(float2*)&Dh[r * DHS2 + cc]       = lo;
                    *(float2*)&Dh[(r + 8) * DHS2 + cc] = hi;
                }
            }
        }
        __syncthreads();
        #pragma unroll 1
        for (int i = t; i < 2048; i += NT) {
            const int r   = i >> 5;
            const int c4  = (i & 31) * 4;
            const int row = base + pg * 64 + r;
            if (row < TOTAL_NODES)
                *(float4*)&g_H[(size_t)row * OUT + c4] = *(const float4*)&Dh[r * DHS2 + c4];
        }
        __syncthreads();
    }
}

// ---------------------------------------------------------------------------
// decode: out = H @ dw + db (unchanged)
// ---------------------------------------------------------------------------
__global__ __launch_bounds__(256) void decode_kernel(
    const float* __restrict__ dw, const float* __restrict__ db,
    float* __restrict__ out)
{
    __shared__ __align__(16) float hsm[DPB][OUT];

    const int base = blockIdx.x * DPB;
    const int t = threadIdx.x;

    for (int i = t; i < DPB * OUT; i += 256)
        hsm[i / OUT][i % OUT] = g_H[(size_t)base * OUT + i];
    __syncthreads();

    const int o   = t & (IN_DIM - 1);
    const int nb0 = (t >> 6) * (DPB / 4);
    float acc[DPB / 4];
    {
        const float bb = db[o];
        #pragma unroll
        for (int n = 0; n < DPB / 4; n++) acc[n] = bb;
    }
    #pragma unroll 4
    for (int k = 0; k < OUT; k += 4) {
        const float w0 = dw[(k + 0) * IN_DIM + o];
        const float w1 = dw[(k + 1) * IN_DIM + o];
        const float w2 = dw[(k + 2) * IN_DIM + o];
        const float w3 = dw[(k + 3) * IN_DIM + o];
        #pragma unroll
        for (int n = 0; n < DPB / 4; n++) {
            float4 v = *reinterpret_cast<const float4*>(&hsm[nb0 + n][k]);
            acc[n] = fmaf(v.x, w0, acc[n]);
            acc[n] = fmaf(v.y, w1, acc[n]);
            acc[n] = fmaf(v.z, w2, acc[n]);
            acc[n] = fmaf(v.w, w3, acc[n]);
        }
    }
    #pragma unroll
    for (int n = 0; n < DPB / 4; n++)
        out[(size_t)(base + nb0 + n) * IN_DIM + o] = acc[n];
}

// ---------------------------------------------------------------------------
extern "C" void kernel_launch(void* const* d_in, const int* in_sizes, int n_in,
                              void* d_out, int out_size)
{
    const float* x   = (const float*)d_in[0];
    const int*   e32 = (const int*)d_in[1];
    const float* ew1 = (const float*)d_in[2];
    const float* eb1 = (const float*)d_in[3];
    const float* ew2 = (const float*)d_in[4];
    const float* eb2 = (const float*)d_in[5];
    const float* nw1 = (const float*)d_in[6];
    const float* nb1 = (const float*)d_in[7];
    const float* nw2 = (const float*)d_in[8];
    const float* nb2 = (const float*)d_in[9];
    const float* dw  = (const float*)d_in[10];
    const float* db  = (const float*)d_in[11];
    float*       out = (float*)d_out;

    static bool attr_done = false;
    if (!attr_done) {
        cudaFuncSetAttribute(edge_mlp_tc_kernel,
            cudaFuncAttributeMaxDynamicSharedMemorySize, EDGE_DSMEM);
        cudaFuncSetAttribute(node_mlp_tc_kernel,
            cudaFuncAttributeMaxDynamicSharedMemorySize, NODE_DSMEM);
        attr_done = true;
    }

    detect_edge_dtype_kernel<<<1, 32>>>(e32);
    convert_edges_kernel<<<(NEDGE + 255) / 256, 256>>>(e32);
    prep_weights_kernel<<<128, 256>>>(ew1, ew2, nw1, nw2);

    node_mlp_tc_kernel<<<(TOTAL_NODES + 127) / 128, NT, NODE_DSMEM>>>(x, nb1, nb2);

    edge_mlp_tc_kernel<<<(NEDGE + 63) / 64, NT, EDGE_DSMEM>>>(x, eb1, eb2);

    decode_kernel<<<TOTAL_NODES / DPB, 256>>>(dw, db, out);
}